// round 6
// baseline (speedup 1.0000x reference)
#include <cuda_runtime.h>
#include <cuda_bf16.h>
#include <math.h>

#define BD   2
#define SEQ  1024
#define DM   768
#define NH   12
#define HD   64
#define GD   192
#define ATT_SCALE 0.125f

typedef __nv_bfloat16 bf16;

// ------------------------------ scratch ------------------------------------
__device__ __align__(16) bf16 g_qw[BD*NH*SEQ*HD];
__device__ __align__(16) bf16 g_qr[BD*NH*SEQ*HD];
__device__ __align__(16) bf16 g_k [BD*NH*SEQ*HD];
__device__ __align__(16) bf16 g_v [BD*NH*SEQ*HD];
__device__ __align__(16) bf16 g_rh[NH*2048*HD];
__device__ __align__(16) bf16 g_avh[BD*SEQ*DM];
__device__ __align__(16) bf16 g_avl[BD*SEQ*DM];
__device__ __align__(16) bf16 g_woh[DM*DM];
__device__ __align__(16) bf16 g_wol[DM*DM];
__device__ float g_h [BD*SEQ*DM];

// ------------------------------ helpers ------------------------------------
__device__ __forceinline__ unsigned pk(float lo, float hi) {
    __nv_bfloat162 h = __floats2bfloat162_rn(lo, hi);
    return *(unsigned*)&h;
}
__device__ __forceinline__ unsigned s2u(const void* p) {
    return (unsigned)__cvta_generic_to_shared(p);
}
__device__ __forceinline__ void ldm_x4(unsigned& r0, unsigned& r1, unsigned& r2, unsigned& r3, unsigned a) {
    asm volatile("ldmatrix.sync.aligned.m8n8.x4.shared.b16 {%0,%1,%2,%3},[%4];"
                 : "=r"(r0), "=r"(r1), "=r"(r2), "=r"(r3) : "r"(a));
}
__device__ __forceinline__ void ldm_x2(unsigned& r0, unsigned& r1, unsigned a) {
    asm volatile("ldmatrix.sync.aligned.m8n8.x2.shared.b16 {%0,%1},[%2];"
                 : "=r"(r0), "=r"(r1) : "r"(a));
}
__device__ __forceinline__ void ldm_x2t(unsigned& r0, unsigned& r1, unsigned a) {
    asm volatile("ldmatrix.sync.aligned.m8n8.x2.trans.shared.b16 {%0,%1},[%2];"
                 : "=r"(r0), "=r"(r1) : "r"(a));
}
__device__ __forceinline__ void mma_bf16(float* c, const unsigned* a, unsigned b0, unsigned b1) {
    asm volatile("mma.sync.aligned.m16n8k16.row.col.f32.bf16.bf16.f32 "
                 "{%0,%1,%2,%3},{%4,%5,%6,%7},{%8,%9},{%0,%1,%2,%3};"
                 : "+f"(c[0]), "+f"(c[1]), "+f"(c[2]), "+f"(c[3])
                 : "r"(a[0]), "r"(a[1]), "r"(a[2]), "r"(a[3]), "r"(b0), "r"(b1));
}

// 64x64 fp32 tile -> bf16 swizzled smem (128B rows, 16B chunk XOR swizzle)
__device__ __forceinline__ void load_conv_tile(bf16* dst, const float* src, int ld,
                                               int valid_rows, int tid) {
    #pragma unroll
    for (int it = 0; it < 4; it++) {
        int c = tid + it*128, row = c >> 3, ch = c & 7;
        uint4 w = make_uint4(0u,0u,0u,0u);
        if (row < valid_rows) {
            const float* p = src + (size_t)row*ld + ch*8;
            float4 u = *(const float4*)p;
            float4 v = *(const float4*)(p+4);
            w.x = pk(u.x,u.y); w.y = pk(u.z,u.w);
            w.z = pk(v.x,v.y); w.w = pk(v.z,v.w);
        }
        *(uint4*)((char*)dst + row*128 + ((ch ^ (row&7)) << 4)) = w;
    }
}
// 64x64 bf16 tile copy (arbitrary row stride in elements) -> swizzled smem
__device__ __forceinline__ void copy_bf16_tile(bf16* dst, const bf16* src, int ld, int tid) {
    #pragma unroll
    for (int it = 0; it < 4; it++) {
        int c = tid + it*128, row = c >> 3, ch = c & 7;
        uint4 v = *(const uint4*)(src + (size_t)row*ld + ch*8);
        *(uint4*)((char*)dst + row*128 + ((ch ^ (row&7)) << 4)) = v;
    }
}

// compute one 64x64 tile: c += A(sA) @ B(sB), warp w rows w*16..+15
__device__ __forceinline__ void mma_tile(float (*c)[4], const bf16* sA, const bf16* sB,
                                         int lane, int w) {
    unsigned a[4][4];
    int arow = w*16 + (lane & 15), csel = lane >> 4;
    #pragma unroll
    for (int ks = 0; ks < 4; ks++) {
        int ch = ks*2 + csel;
        ldm_x4(a[ks][0], a[ks][1], a[ks][2], a[ks][3],
               s2u((const char*)sA + arow*128 + ((ch ^ (arow&7)) << 4)));
    }
    #pragma unroll
    for (int nb = 0; nb < 8; nb++) {
        #pragma unroll
        for (int ks = 0; ks < 4; ks++) {
            int vrow = ks*16 + (lane & 15);
            unsigned b0, b1;
            ldm_x2t(b0, b1, s2u((const char*)sB + vrow*128 + ((nb ^ (vrow&7)) << 4)));
            mma_bf16(c[nb], a[ks], b0, b1);
        }
    }
}

// ---------------------------------------------------------------------------
// K0: split Wo into bf16 hi/lo.  grid 576, 256 thr
// ---------------------------------------------------------------------------
__global__ void __launch_bounds__(256) wo_prep(const float* __restrict__ Wo)
{
    int i = (blockIdx.x*256 + threadIdx.x) * 4;
    float4 v = *(const float4*)&Wo[i];
    unsigned h0 = pk(v.x, v.y), h1 = pk(v.z, v.w);
    __nv_bfloat162 a = *(__nv_bfloat162*)&h0, b = *(__nv_bfloat162*)&h1;
    unsigned l0 = pk(v.x - __low2float(a), v.y - __high2float(a));
    unsigned l1 = pk(v.z - __low2float(b), v.w - __high2float(b));
    *(uint2*)&g_woh[i] = make_uint2(h0, h1);
    *(uint2*)&g_wol[i] = make_uint2(l0, l1);
}

// ---------------------------------------------------------------------------
// K1: grouped QKV projection (bf16 MMA).  grid (32, 12, 3), 128 thr
// ---------------------------------------------------------------------------
__global__ void __launch_bounds__(128) qkv_kernel(
    const float* __restrict__ x,
    const float* __restrict__ Wq, const float* __restrict__ Wk, const float* __restrict__ bk,
    const float* __restrict__ Wv, const float* __restrict__ bv,
    const float* __restrict__ rwb, const float* __restrict__ rrb)
{
    __shared__ bf16 sA[64*64], sB[64*64];
    const int tid = threadIdx.x, lane = tid & 31, w = tid >> 5;
    const int m0 = blockIdx.x * 64;
    const int g  = blockIdx.y / 3, oo0 = (blockIdx.y % 3) * 64;
    const int z  = blockIdx.z;
    const float* W = ((z == 0) ? Wq : (z == 1) ? Wk : Wv) + g * GD * GD;
    float c[8][4] = {};

    for (int kb = 0; kb < GD; kb += 64) {
        __syncthreads();
        load_conv_tile(sA, x + (size_t)m0*DM + g*GD + kb, DM, 64, tid);
        load_conv_tile(sB, W + (size_t)kb*GD + oo0, GD, 64, tid);
        __syncthreads();
        mma_tile(c, sA, sB, lane, w);
    }

    const int n = blockIdx.y;                 // 3g + oo0/64
    const int o0g = g*GD + oo0;
    const int r0 = w*16 + (lane >> 2), q2 = 2*(lane & 3);
    const int b = m0 >> 10;
    const int s0 = (m0 & 1023) + r0;
    #pragma unroll
    for (int nb = 0; nb < 8; nb++) {
        int d = nb*8 + q2, bi = o0g + d;
        size_t ob0 = (((size_t)(b*NH + n))*SEQ + s0)*HD + d;
        size_t ob1 = ob0 + 8*HD;
        if (z == 0) {
            float w0 = rwb[bi], w1 = rwb[bi+1], r0b = rrb[bi], r1b = rrb[bi+1];
            *(unsigned*)&g_qw[ob0] = pk((c[nb][0]+w0)*ATT_SCALE, (c[nb][1]+w1)*ATT_SCALE);
            *(unsigned*)&g_qw[ob1] = pk((c[nb][2]+w0)*ATT_SCALE, (c[nb][3]+w1)*ATT_SCALE);
            *(unsigned*)&g_qr[ob0] = pk((c[nb][0]+r0b)*ATT_SCALE, (c[nb][1]+r1b)*ATT_SCALE);
            *(unsigned*)&g_qr[ob1] = pk((c[nb][2]+r0b)*ATT_SCALE, (c[nb][3]+r1b)*ATT_SCALE);
        } else if (z == 1) {
            float b0 = bk[bi], b1 = bk[bi+1];
            *(unsigned*)&g_k[ob0] = pk(c[nb][0]+b0, c[nb][1]+b1);
            *(unsigned*)&g_k[ob1] = pk(c[nb][2]+b0, c[nb][3]+b1);
        } else {
            float b0 = bv[bi], b1 = bv[bi+1];
            *(unsigned*)&g_v[ob0] = pk(c[nb][0]+b0, c[nb][1]+b1);
            *(unsigned*)&g_v[ob1] = pk(c[nb][2]+b0, c[nb][3]+b1);
        }
    }
}

// ---------------------------------------------------------------------------
// K2: r_head = position_embeds @ r_kernel (bf16 MMA).  grid (32, 12), 128 thr
// ---------------------------------------------------------------------------
__global__ void __launch_bounds__(128) rhead_kernel(
    const float* __restrict__ pe, const float* __restrict__ rk)
{
    __shared__ bf16 sA[64*64], sB[64*64];
    const int tid = threadIdx.x, lane = tid & 31, w = tid >> 5;
    const int t0 = blockIdx.x * 64;
    const int o0 = blockIdx.y * 64;
    const int vr = min(64, 2047 - t0);
    float c[8][4] = {};

    for (int kb = 0; kb < DM; kb += 64) {
        __syncthreads();
        load_conv_tile(sA, pe + (size_t)t0*DM + kb, DM, vr, tid);
        load_conv_tile(sB, rk + (size_t)kb*DM + o0, DM, 64, tid);
        __syncthreads();
        mma_tile(c, sA, sB, lane, w);
    }

    const int n = blockIdx.y;
    const int r0 = w*16 + (lane >> 2), q2 = 2*(lane & 3);
    #pragma unroll
    for (int nb = 0; nb < 8; nb++) {
        int d = nb*8 + q2;
        size_t ob0 = ((size_t)n*2048 + t0 + r0)*HD + d;
        *(unsigned*)&g_rh[ob0]        = pk(c[nb][0], c[nb][1]);
        *(unsigned*)&g_rh[ob0 + 8*HD] = pk(c[nb][2], c[nb][3]);
    }
}

// ---------------------------------------------------------------------------
// K3: flash attention, bf16 HMMA, pos' sliding-window ring. grid (16, 24), 128 thr
// ---------------------------------------------------------------------------
#define RING_PITCH 132
#define ATT_SMEM_BYTES (40960 + 64*RING_PITCH*4)

__device__ __forceinline__ void copy_tile64(bf16* dst, const bf16* src, int tid) {
    #pragma unroll
    for (int k = 0; k < 4; k++) {
        int c = tid + k*128, row = c >> 3, ch = c & 7;
        uint4 v = *(const uint4*)(src + (size_t)row*64 + ch*8);
        *(uint4*)((char*)dst + row*128 + ((ch ^ (row & 7)) << 4)) = v;
    }
}
__device__ __forceinline__ void load_rh_tile(bf16* dst, const bf16* src, int Tc, int tid) {
    #pragma unroll
    for (int k = 0; k < 4; k++) {
        int c = tid + k*128, row = c >> 3, ch = c & 7;
        int t = Tc + row;
        uint4 v = make_uint4(0u,0u,0u,0u);
        if (t < 2048) v = *(const uint4*)(src + (size_t)t*64 + ch*8);
        *(uint4*)((char*)dst + row*128 + ((ch ^ (row & 7)) << 4)) = v;
    }
}

__device__ __forceinline__ void pos_mma_ring(
    const bf16* sRh, float* ring, const unsigned (*qrA)[4],
    int Tc, int lane, int r0, int q2)
{
    #pragma unroll
    for (int nb = 0; nb < 8; nb++) {
        float pc[4] = {0.f, 0.f, 0.f, 0.f};
        int brow = nb*8 + (lane & 7);
        #pragma unroll
        for (int ks = 0; ks < 4; ks++) {
            int ch = ks*2 + ((lane >> 3) & 1);
            unsigned b0, b1;
            ldm_x2(b0, b1, s2u((const char*)sRh + brow*128 + ((ch ^ (brow & 7)) << 4)));
            mma_bf16(pc, qrA[ks], b0, b1);
        }
        int s0 = (Tc + nb*8 + q2) & 127;
        int s1 = (s0 + 1) & 127;
        ring[r0*RING_PITCH + s0]     = pc[0];
        ring[r0*RING_PITCH + s1]     = pc[1];
        ring[(r0+8)*RING_PITCH + s0] = pc[2];
        ring[(r0+8)*RING_PITCH + s1] = pc[3];
    }
}

__global__ void __launch_bounds__(128) attn_kernel()
{
    extern __shared__ char smc[];
    bf16*  sQw  = (bf16*)(smc);
    bf16*  sQr  = (bf16*)(smc + 8192);
    bf16*  sK   = (bf16*)(smc + 16384);
    bf16*  sRh  = (bf16*)(smc + 24576);
    bf16*  sV   = (bf16*)(smc + 32768);
    float* ring = (float*)(smc + 40960);

    const int tid = threadIdx.x, lane = tid & 31, w = tid >> 5;
    const int bn = blockIdx.y, n = bn % NH, b = bn / NH;
    const int i0 = blockIdx.x * 64;

    const bf16* qwB = g_qw + (size_t)bn * SEQ * HD;
    const bf16* qrB = g_qr + (size_t)bn * SEQ * HD;
    const bf16* kB  = g_k  + (size_t)bn * SEQ * HD;
    const bf16* vB  = g_v  + (size_t)bn * SEQ * HD;
    const bf16* rhB = g_rh + (size_t)n * 2048 * HD;

    copy_tile64(sQw, qwB + (size_t)i0*HD, tid);
    copy_tile64(sQr, qrB + (size_t)i0*HD, tid);
    load_rh_tile(sRh, rhB, 961 - i0, tid);
    __syncthreads();

    unsigned qwA[4][4], qrA[4][4];
    {
        int arow = w*16 + (lane & 15);
        int csel = lane >> 4;
        #pragma unroll
        for (int ks = 0; ks < 4; ks++) {
            int ch = ks*2 + csel;
            unsigned off = ((ch ^ (arow & 7)) << 4) + arow*128;
            ldm_x4(qwA[ks][0], qwA[ks][1], qwA[ks][2], qwA[ks][3], s2u((char*)sQw + off));
            ldm_x4(qrA[ks][0], qrA[ks][1], qrA[ks][2], qrA[ks][3], s2u((char*)sQr + off));
        }
    }

    const int r0 = w*16 + (lane >> 2);
    const int q2 = 2*(lane & 3);

    float o[8][4] = {};
    float mrow0 = -INFINITY, mrow1 = -INFINITY, lrow0 = 0.f, lrow1 = 0.f;

    pos_mma_ring(sRh, ring, qrA, 961 - i0, lane, r0, q2);

    for (int j0 = 0; j0 < SEQ; j0 += 64) {
        __syncthreads();
        copy_tile64(sK, kB + (size_t)j0*HD, tid);
        copy_tile64(sV, vB + (size_t)j0*HD, tid);
        const int Tc = 1025 + j0 - i0;
        load_rh_tile(sRh, rhB, Tc, tid);
        __syncthreads();

        float c[8][4] = {};
        #pragma unroll
        for (int nb = 0; nb < 8; nb++) {
            int brow = nb*8 + (lane & 7);
            #pragma unroll
            for (int ks = 0; ks < 4; ks++) {
                int ch = ks*2 + ((lane >> 3) & 1);
                unsigned b0, b1;
                ldm_x2(b0, b1, s2u((char*)sK + brow*128 + ((ch ^ (brow & 7)) << 4)));
                mma_bf16(c[nb], qwA[ks], b0, b1);
            }
        }
        pos_mma_ring(sRh, ring, qrA, Tc, lane, r0, q2);
        __syncthreads();

        #pragma unroll
        for (int nb = 0; nb < 8; nb++) {
            int jl = nb*8 + q2;
            int ta = 1024 + j0 + jl - (i0 + r0);
            c[nb][0] += ring[r0*RING_PITCH + (ta & 127)];
            c[nb][1] += ring[r0*RING_PITCH + ((ta + 1) & 127)];
            int tb = ta - 8;
            c[nb][2] += ring[(r0+8)*RING_PITCH + (tb & 127)];
            c[nb][3] += ring[(r0+8)*RING_PITCH + ((tb + 1) & 127)];
        }
        if (i0 == 0 && j0 == 960 && tid == 3) {
            float s = 0.f;
            #pragma unroll
            for (int d = 0; d < HD; d++)
                s += __bfloat162float(qrB[HD + d]) * __bfloat162float(rhB[d]);
            c[7][1] += s;
        }

        float mx0 = -INFINITY, mx1 = -INFINITY;
        #pragma unroll
        for (int nb = 0; nb < 8; nb++) {
            mx0 = fmaxf(mx0, fmaxf(c[nb][0], c[nb][1]));
            mx1 = fmaxf(mx1, fmaxf(c[nb][2], c[nb][3]));
        }
        mx0 = fmaxf(mx0, __shfl_xor_sync(0xffffffffu, mx0, 1));
        mx0 = fmaxf(mx0, __shfl_xor_sync(0xffffffffu, mx0, 2));
        mx1 = fmaxf(mx1, __shfl_xor_sync(0xffffffffu, mx1, 1));
        mx1 = fmaxf(mx1, __shfl_xor_sync(0xffffffffu, mx1, 2));
        float mn0 = fmaxf(mrow0, mx0), mn1 = fmaxf(mrow1, mx1);
        float sc0 = __expf(mrow0 - mn0), sc1 = __expf(mrow1 - mn1);
        mrow0 = mn0; mrow1 = mn1;
        float s0 = 0.f, s1 = 0.f;
        #pragma unroll
        for (int nb = 0; nb < 8; nb++) {
            c[nb][0] = __expf(c[nb][0] - mn0); s0 += c[nb][0];
            c[nb][1] = __expf(c[nb][1] - mn0); s0 += c[nb][1];
            c[nb][2] = __expf(c[nb][2] - mn1); s1 += c[nb][2];
            c[nb][3] = __expf(c[nb][3] - mn1); s1 += c[nb][3];
        }
        s0 += __shfl_xor_sync(0xffffffffu, s0, 1);
        s0 += __shfl_xor_sync(0xffffffffu, s0, 2);
        s1 += __shfl_xor_sync(0xffffffffu, s1, 1);
        s1 += __shfl_xor_sync(0xffffffffu, s1, 2);
        lrow0 = lrow0*sc0 + s0; lrow1 = lrow1*sc1 + s1;
        #pragma unroll
        for (int nb = 0; nb < 8; nb++) {
            o[nb][0] *= sc0; o[nb][1] *= sc0;
            o[nb][2] *= sc1; o[nb][3] *= sc1;
        }

        unsigned pa[4][4];
        #pragma unroll
        for (int ks = 0; ks < 4; ks++) {
            pa[ks][0] = pk(c[2*ks][0],   c[2*ks][1]);
            pa[ks][1] = pk(c[2*ks][2],   c[2*ks][3]);
            pa[ks][2] = pk(c[2*ks+1][0], c[2*ks+1][1]);
            pa[ks][3] = pk(c[2*ks+1][2], c[2*ks+1][3]);
        }
        #pragma unroll
        for (int nb = 0; nb < 8; nb++) {
            #pragma unroll
            for (int ks = 0; ks < 4; ks++) {
                int vrow = ks*16 + (lane & 15);
                unsigned b0, b1;
                ldm_x2t(b0, b1, s2u((char*)sV + vrow*128 + ((nb ^ (vrow & 7)) << 4)));
                mma_bf16(o[nb], pa[ks], b0, b1);
            }
        }
    }

    // epilogue: normalize + split into bf16 hi/lo
    float inv0 = 1.f / lrow0, inv1 = 1.f / lrow1;
    #pragma unroll
    for (int nb = 0; nb < 8; nb++) {
        int dd = nb*8 + q2;
        float a0 = o[nb][0]*inv0, a1 = o[nb][1]*inv0;
        float b0 = o[nb][2]*inv1, b1 = o[nb][3]*inv1;
        unsigned h0 = pk(a0, a1), h1 = pk(b0, b1);
        __nv_bfloat162 x0 = *(__nv_bfloat162*)&h0, x1 = *(__nv_bfloat162*)&h1;
        unsigned l0 = pk(a0 - __low2float(x0), a1 - __high2float(x0));
        unsigned l1 = pk(b0 - __low2float(x1), b1 - __high2float(x1));
        size_t ob0 = ((size_t)(b*SEQ + i0 + r0))*DM + n*HD + dd;
        size_t ob1 = ob0 + 8*DM;
        *(unsigned*)&g_avh[ob0] = h0;  *(unsigned*)&g_avl[ob0] = l0;
        *(unsigned*)&g_avh[ob1] = h1;  *(unsigned*)&g_avl[ob1] = l1;
    }
}

// ---------------------------------------------------------------------------
// K4: h = query + av @ Wo + bo  (split-bf16 MMA).  grid (32, 12), 128 thr
// ---------------------------------------------------------------------------
__global__ void __launch_bounds__(128) proj_kernel(
    const float* __restrict__ bo, const float* __restrict__ x)
{
    __shared__ bf16 sAh[64*64], sAl[64*64], sBh[64*64], sBl[64*64];
    const int tid = threadIdx.x, lane = tid & 31, w = tid >> 5;
    const int m0 = blockIdx.x * 64;
    const int o0 = blockIdx.y * 64;
    float c[8][4] = {};

    for (int kb = 0; kb < DM; kb += 64) {
        __syncthreads();
        copy_bf16_tile(sAh, g_avh + (size_t)m0*DM + kb, DM, tid);
        copy_bf16_tile(sAl, g_avl + (size_t)m0*DM + kb, DM, tid);
        copy_bf16_tile(sBh, g_woh + (size_t)kb*DM + o0, DM, tid);
        copy_bf16_tile(sBl, g_wol + (size_t)kb*DM + o0, DM, tid);
        __syncthreads();

        unsigned ah[4][4], al[4][4];
        int arow = w*16 + (lane & 15), csel = lane >> 4;
        #pragma unroll
        for (int ks = 0; ks < 4; ks++) {
            int ch = ks*2 + csel;
            unsigned off = arow*128 + ((ch ^ (arow&7)) << 4);
            ldm_x4(ah[ks][0], ah[ks][1], ah[ks][2], ah[ks][3], s2u((char*)sAh + off));
            ldm_x4(al[ks][0], al[ks][1], al[ks][2], al[ks][3], s2u((char*)sAl + off));
        }
        #pragma unroll
        for (int nb = 0; nb < 8; nb++) {
            #pragma unroll
            for (int ks = 0; ks < 4; ks++) {
                int vrow = ks*16 + (lane & 15);
                unsigned off = vrow*128 + ((nb ^ (vrow&7)) << 4);
                unsigned bh0, bh1, bl0, bl1;
                ldm_x2t(bh0, bh1, s2u((char*)sBh + off));
                ldm_x2t(bl0, bl1, s2u((char*)sBl + off));
                mma_bf16(c[nb], ah[ks], bh0, bh1);
                mma_bf16(c[nb], al[ks], bh0, bh1);
                mma_bf16(c[nb], ah[ks], bl0, bl1);
            }
        }
    }

    const int r0 = w*16 + (lane >> 2), q2 = 2*(lane & 3);
    #pragma unroll
    for (int nb = 0; nb < 8; nb++) {
        int col = o0 + nb*8 + q2;
        float b0 = bo[col], b1 = bo[col+1];
        size_t ob0 = (size_t)(m0 + r0)*DM + col;
        size_t ob1 = ob0 + 8*DM;
        float2 q0 = *(const float2*)&x[ob0];
        float2 q1 = *(const float2*)&x[ob1];
        *(float2*)&g_h[ob0] = make_float2(c[nb][0] + b0 + q0.x, c[nb][1] + b1 + q0.y);
        *(float2*)&g_h[ob1] = make_float2(c[nb][2] + b0 + q1.x, c[nb][3] + b1 + q1.y);
    }
}

// ---------------------------------------------------------------------------
// K5: LayerNorm.  grid (2048), 256 threads
// ---------------------------------------------------------------------------
__global__ void __launch_bounds__(256) ln_kernel(
    const float* __restrict__ gamma, const float* __restrict__ beta,
    float* __restrict__ out)
{
    __shared__ float red[16];
    const int row = blockIdx.x;
    const int tid = threadIdx.x;
    const float* h = g_h + (size_t)row * DM;
    float v0 = h[tid], v1 = h[tid+256], v2 = h[tid+512];
    float s = v0+v1+v2, ss = v0*v0+v1*v1+v2*v2;
    #pragma unroll
    for (int o = 16; o >= 1; o >>= 1) {
        s  += __shfl_xor_sync(0xffffffffu, s,  o);
        ss += __shfl_xor_sync(0xffffffffu, ss, o);
    }
    if ((tid & 31) == 0) { red[tid>>5] = s; red[8 + (tid>>5)] = ss; }
    __syncthreads();
    if (tid < 32) {
        float a = (tid < 8)  ? red[tid]     : 0.f;
        float b = (tid < 8)  ? red[8+tid]   : 0.f;
        #pragma unroll
        for (int o = 4; o >= 1; o >>= 1) {
            a += __shfl_xor_sync(0xffffffffu, a, o);
            b += __shfl_xor_sync(0xffffffffu, b, o);
        }
        if (tid == 0) { red[0] = a; red[1] = b; }
    }
    __syncthreads();
    float mu  = red[0] * (1.f/DM);
    float var = red[1] * (1.f/DM) - mu*mu;
    float inv = rsqrtf(var + 1e-9f);
    out[(size_t)row*DM + tid]     = (v0 - mu)*inv*gamma[tid]     + beta[tid];
    out[(size_t)row*DM + tid+256] = (v1 - mu)*inv*gamma[tid+256] + beta[tid+256];
    out[(size_t)row*DM + tid+512] = (v2 - mu)*inv*gamma[tid+512] + beta[tid+512];
}

// ---------------------------------------------------------------------------
extern "C" void kernel_launch(void* const* d_in, const int* in_sizes, int n_in,
                              void* d_out, int out_size)
{
    const float* query = (const float*)d_in[0];
    const float* pe    = (const float*)d_in[1];
    const float* Wq    = (const float*)d_in[2];
    const float* Wk    = (const float*)d_in[3];
    const float* bk    = (const float*)d_in[4];
    const float* Wv    = (const float*)d_in[5];
    const float* bv    = (const float*)d_in[6];
    const float* rk    = (const float*)d_in[7];
    const float* rwb   = (const float*)d_in[8];
    const float* rrb   = (const float*)d_in[9];
    const float* Wo    = (const float*)d_in[10];
    const float* bo    = (const float*)d_in[11];
    const float* gamma = (const float*)d_in[12];
    const float* beta  = (const float*)d_in[13];
    float* out = (float*)d_out;

    static bool attr_set = false;
    if (!attr_set) {
        cudaFuncSetAttribute(attn_kernel,
            cudaFuncAttributeMaxDynamicSharedMemorySize, ATT_SMEM_BYTES);
        attr_set = true;
    }

    wo_prep<<<DM*DM/1024, 256>>>(Wo);
    qkv_kernel<<<dim3(32,12,3), 128>>>(query, Wq, Wk, bk, Wv, bv, rwb, rrb);
    rhead_kernel<<<dim3(32,12), 128>>>(pe, rk);
    attn_kernel<<<dim3(16,24), 128, ATT_SMEM_BYTES>>>();
    proj_kernel<<<dim3(32,12), 128>>>(bo, query);
    ln_kernel<<<2048, 256>>>(gamma, beta, out);
}

// round 7
// speedup vs baseline: 1.0289x; 1.0289x over previous
#include <cuda_runtime.h>
#include <cuda_bf16.h>
#include <math.h>

#define BD   2
#define SEQ  1024
#define DM   768
#define NH   12
#define HD   64
#define GD   192
#define ATT_SCALE 0.125f

typedef __nv_bfloat16 bf16;

// ------------------------------ scratch ------------------------------------
__device__ __align__(16) bf16 g_qw[BD*NH*SEQ*HD];
__device__ __align__(16) bf16 g_qr[BD*NH*SEQ*HD];
__device__ __align__(16) bf16 g_k [BD*NH*SEQ*HD];
__device__ __align__(16) bf16 g_v [BD*NH*SEQ*HD];
__device__ __align__(16) bf16 g_rh[NH*2048*HD];
__device__ __align__(16) bf16 g_avh[BD*SEQ*DM];
__device__ __align__(16) bf16 g_avl[BD*SEQ*DM];
__device__ __align__(16) bf16 g_woh[DM*DM];
__device__ __align__(16) bf16 g_wol[DM*DM];
__device__ float g_h [BD*SEQ*DM];

// ------------------------------ helpers ------------------------------------
__device__ __forceinline__ unsigned pk(float lo, float hi) {
    __nv_bfloat162 h = __floats2bfloat162_rn(lo, hi);
    return *(unsigned*)&h;
}
__device__ __forceinline__ unsigned s2u(const void* p) {
    return (unsigned)__cvta_generic_to_shared(p);
}
__device__ __forceinline__ void ldm_x4(unsigned& r0, unsigned& r1, unsigned& r2, unsigned& r3, unsigned a) {
    asm volatile("ldmatrix.sync.aligned.m8n8.x4.shared.b16 {%0,%1,%2,%3},[%4];"
                 : "=r"(r0), "=r"(r1), "=r"(r2), "=r"(r3) : "r"(a));
}
__device__ __forceinline__ void ldm_x4t(unsigned& r0, unsigned& r1, unsigned& r2, unsigned& r3, unsigned a) {
    asm volatile("ldmatrix.sync.aligned.m8n8.x4.trans.shared.b16 {%0,%1,%2,%3},[%4];"
                 : "=r"(r0), "=r"(r1), "=r"(r2), "=r"(r3) : "r"(a));
}
__device__ __forceinline__ void mma_bf16(float* c, const unsigned* a, unsigned b0, unsigned b1) {
    asm volatile("mma.sync.aligned.m16n8k16.row.col.f32.bf16.bf16.f32 "
                 "{%0,%1,%2,%3},{%4,%5,%6,%7},{%8,%9},{%0,%1,%2,%3};"
                 : "+f"(c[0]), "+f"(c[1]), "+f"(c[2]), "+f"(c[3])
                 : "r"(a[0]), "r"(a[1]), "r"(a[2]), "r"(a[3]), "r"(b0), "r"(b1));
}

// 64x64 fp32 tile -> bf16 swizzled smem (128B rows, 16B chunk XOR swizzle)
__device__ __forceinline__ void load_conv_tile(bf16* dst, const float* src, int ld,
                                               int valid_rows, int tid) {
    #pragma unroll
    for (int it = 0; it < 4; it++) {
        int c = tid + it*128, row = c >> 3, ch = c & 7;
        uint4 w = make_uint4(0u,0u,0u,0u);
        if (row < valid_rows) {
            const float* p = src + (size_t)row*ld + ch*8;
            float4 u = *(const float4*)p;
            float4 v = *(const float4*)(p+4);
            w.x = pk(u.x,u.y); w.y = pk(u.z,u.w);
            w.z = pk(v.x,v.y); w.w = pk(v.z,v.w);
        }
        *(uint4*)((char*)dst + row*128 + ((ch ^ (row&7)) << 4)) = w;
    }
}
__device__ __forceinline__ void copy_bf16_tile(bf16* dst, const bf16* src, int ld, int tid) {
    #pragma unroll
    for (int it = 0; it < 4; it++) {
        int c = tid + it*128, row = c >> 3, ch = c & 7;
        uint4 v = *(const uint4*)(src + (size_t)row*ld + ch*8);
        *(uint4*)((char*)dst + row*128 + ((ch ^ (row&7)) << 4)) = v;
    }
}

// one 64x64 tile: c += A(sA) @ B(sB)^T-layout, warp w rows w*16..+15. x4 B loads.
__device__ __forceinline__ void mma_tile(float (*c)[4], const bf16* sA, const bf16* sB,
                                         int lane, int w) {
    unsigned a[4][4];
    int arow = w*16 + (lane & 15), csel = lane >> 4;
    #pragma unroll
    for (int ks = 0; ks < 4; ks++) {
        int ch = ks*2 + csel;
        ldm_x4(a[ks][0], a[ks][1], a[ks][2], a[ks][3],
               s2u((const char*)sA + arow*128 + ((ch ^ (arow&7)) << 4)));
    }
    #pragma unroll
    for (int nbp = 0; nbp < 4; nbp++) {
        #pragma unroll
        for (int ks = 0; ks < 4; ks++) {
            int vrow = ks*16 + (lane & 15);
            int ch   = nbp*2 + (lane >> 4);
            unsigned b0, b1, b2, b3;
            ldm_x4t(b0, b1, b2, b3,
                    s2u((const char*)sB + vrow*128 + ((ch ^ (vrow&7)) << 4)));
            mma_bf16(c[2*nbp],   a[ks], b0, b1);
            mma_bf16(c[2*nbp+1], a[ks], b2, b3);
        }
    }
}

// ---------------------------------------------------------------------------
// K0: split Wo into bf16 hi/lo.  grid 576, 256 thr
// ---------------------------------------------------------------------------
__global__ void __launch_bounds__(256) wo_prep(const float* __restrict__ Wo)
{
    int i = (blockIdx.x*256 + threadIdx.x) * 4;
    float4 v = *(const float4*)&Wo[i];
    unsigned h0 = pk(v.x, v.y), h1 = pk(v.z, v.w);
    __nv_bfloat162 a = *(__nv_bfloat162*)&h0, b = *(__nv_bfloat162*)&h1;
    unsigned l0 = pk(v.x - __low2float(a), v.y - __high2float(a));
    unsigned l1 = pk(v.z - __low2float(b), v.w - __high2float(b));
    *(uint2*)&g_woh[i] = make_uint2(h0, h1);
    *(uint2*)&g_wol[i] = make_uint2(l0, l1);
}

// ---------------------------------------------------------------------------
// K1: grouped QKV projection (bf16 MMA).  grid (32, 12, 3), 128 thr
// ---------------------------------------------------------------------------
__global__ void __launch_bounds__(128) qkv_kernel(
    const float* __restrict__ x,
    const float* __restrict__ Wq, const float* __restrict__ Wk, const float* __restrict__ bk,
    const float* __restrict__ Wv, const float* __restrict__ bv,
    const float* __restrict__ rwb, const float* __restrict__ rrb)
{
    __shared__ bf16 sA[64*64], sB[64*64];
    const int tid = threadIdx.x, lane = tid & 31, w = tid >> 5;
    const int m0 = blockIdx.x * 64;
    const int g  = blockIdx.y / 3, oo0 = (blockIdx.y % 3) * 64;
    const int z  = blockIdx.z;
    const float* W = ((z == 0) ? Wq : (z == 1) ? Wk : Wv) + g * GD * GD;
    float c[8][4] = {};

    for (int kb = 0; kb < GD; kb += 64) {
        __syncthreads();
        load_conv_tile(sA, x + (size_t)m0*DM + g*GD + kb, DM, 64, tid);
        load_conv_tile(sB, W + (size_t)kb*GD + oo0, GD, 64, tid);
        __syncthreads();
        mma_tile(c, sA, sB, lane, w);
    }

    const int n = blockIdx.y;
    const int o0g = g*GD + oo0;
    const int r0 = w*16 + (lane >> 2), q2 = 2*(lane & 3);
    const int b = m0 >> 10;
    const int s0 = (m0 & 1023) + r0;
    #pragma unroll
    for (int nb = 0; nb < 8; nb++) {
        int d = nb*8 + q2, bi = o0g + d;
        size_t ob0 = (((size_t)(b*NH + n))*SEQ + s0)*HD + d;
        size_t ob1 = ob0 + 8*HD;
        if (z == 0) {
            float w0 = rwb[bi], w1 = rwb[bi+1], r0b = rrb[bi], r1b = rrb[bi+1];
            *(unsigned*)&g_qw[ob0] = pk((c[nb][0]+w0)*ATT_SCALE, (c[nb][1]+w1)*ATT_SCALE);
            *(unsigned*)&g_qw[ob1] = pk((c[nb][2]+w0)*ATT_SCALE, (c[nb][3]+w1)*ATT_SCALE);
            *(unsigned*)&g_qr[ob0] = pk((c[nb][0]+r0b)*ATT_SCALE, (c[nb][1]+r1b)*ATT_SCALE);
            *(unsigned*)&g_qr[ob1] = pk((c[nb][2]+r0b)*ATT_SCALE, (c[nb][3]+r1b)*ATT_SCALE);
        } else if (z == 1) {
            float b0 = bk[bi], b1 = bk[bi+1];
            *(unsigned*)&g_k[ob0] = pk(c[nb][0]+b0, c[nb][1]+b1);
            *(unsigned*)&g_k[ob1] = pk(c[nb][2]+b0, c[nb][3]+b1);
        } else {
            float b0 = bv[bi], b1 = bv[bi+1];
            *(unsigned*)&g_v[ob0] = pk(c[nb][0]+b0, c[nb][1]+b1);
            *(unsigned*)&g_v[ob1] = pk(c[nb][2]+b0, c[nb][3]+b1);
        }
    }
}

// ---------------------------------------------------------------------------
// K2: r_head = position_embeds @ r_kernel (bf16 MMA).  grid (32, 12), 128 thr
// ---------------------------------------------------------------------------
__global__ void __launch_bounds__(128) rhead_kernel(
    const float* __restrict__ pe, const float* __restrict__ rk)
{
    __shared__ bf16 sA[64*64], sB[64*64];
    const int tid = threadIdx.x, lane = tid & 31, w = tid >> 5;
    const int t0 = blockIdx.x * 64;
    const int o0 = blockIdx.y * 64;
    const int vr = min(64, 2047 - t0);
    float c[8][4] = {};

    for (int kb = 0; kb < DM; kb += 64) {
        __syncthreads();
        load_conv_tile(sA, pe + (size_t)t0*DM + kb, DM, vr, tid);
        load_conv_tile(sB, rk + (size_t)kb*DM + o0, DM, 64, tid);
        __syncthreads();
        mma_tile(c, sA, sB, lane, w);
    }

    const int n = blockIdx.y;
    const int r0 = w*16 + (lane >> 2), q2 = 2*(lane & 3);
    #pragma unroll
    for (int nb = 0; nb < 8; nb++) {
        int d = nb*8 + q2;
        size_t ob0 = ((size_t)n*2048 + t0 + r0)*HD + d;
        *(unsigned*)&g_rh[ob0]        = pk(c[nb][0], c[nb][1]);
        *(unsigned*)&g_rh[ob0 + 8*HD] = pk(c[nb][2], c[nb][3]);
    }
}

// ---------------------------------------------------------------------------
// K3: flash attention.  smem: [0:8K] Qw->K, [8K:16K] Qr->V, [16K:24K] Rh, ring
// ---------------------------------------------------------------------------
#define RING_PITCH 132
#define ATT_SMEM_BYTES (24576 + 64*RING_PITCH*4)   // 58368

__device__ __forceinline__ void copy_tile64(bf16* dst, const bf16* src, int tid) {
    #pragma unroll
    for (int k = 0; k < 4; k++) {
        int c = tid + k*128, row = c >> 3, ch = c & 7;
        uint4 v = *(const uint4*)(src + (size_t)row*64 + ch*8);
        *(uint4*)((char*)dst + row*128 + ((ch ^ (row & 7)) << 4)) = v;
    }
}
__device__ __forceinline__ void load_rh_tile(bf16* dst, const bf16* src, int Tc, int tid) {
    #pragma unroll
    for (int k = 0; k < 4; k++) {
        int c = tid + k*128, row = c >> 3, ch = c & 7;
        int t = Tc + row;
        uint4 v = make_uint4(0u,0u,0u,0u);
        if (t < 2048) v = *(const uint4*)(src + (size_t)t*64 + ch*8);
        *(uint4*)((char*)dst + row*128 + ((ch ^ (row & 7)) << 4)) = v;
    }
}

// pos' columns for window Tc..Tc+63 into the ring (x4 B loads)
__device__ __forceinline__ void pos_mma_ring(
    const bf16* sRh, float* ring, const unsigned (*qrA)[4],
    int Tc, int lane, int r0, int q2)
{
    #pragma unroll
    for (int nbp = 0; nbp < 4; nbp++) {
        float p0[4] = {0.f,0.f,0.f,0.f}, p1[4] = {0.f,0.f,0.f,0.f};
        int brow = nbp*16 + ((lane >> 4) << 3) + (lane & 7);
        #pragma unroll
        for (int ks = 0; ks < 4; ks++) {
            int ch = ks*2 + ((lane >> 3) & 1);
            unsigned b0, b1, b2, b3;
            ldm_x4(b0, b1, b2, b3,
                   s2u((const char*)sRh + brow*128 + ((ch ^ (brow & 7)) << 4)));
            mma_bf16(p0, qrA[ks], b0, b1);
            mma_bf16(p1, qrA[ks], b2, b3);
        }
        #pragma unroll
        for (int h = 0; h < 2; h++) {
            const float* pc = h ? p1 : p0;
            int s0 = (Tc + (nbp*2+h)*8 + q2) & 127;
            int s1 = (s0 + 1) & 127;
            ring[r0*RING_PITCH + s0]     = pc[0];
            ring[r0*RING_PITCH + s1]     = pc[1];
            ring[(r0+8)*RING_PITCH + s0] = pc[2];
            ring[(r0+8)*RING_PITCH + s1] = pc[3];
        }
    }
}

__global__ void __launch_bounds__(128, 3) attn_kernel()
{
    extern __shared__ char smc[];
    bf16*  sQw  = (bf16*)(smc);            // phase 0
    bf16*  sQr  = (bf16*)(smc + 8192);     // phase 0
    bf16*  sK   = (bf16*)(smc);            // phase 1 (aliases sQw)
    bf16*  sV   = (bf16*)(smc + 8192);     // phase 1 (aliases sQr)
    bf16*  sRh  = (bf16*)(smc + 16384);
    float* ring = (float*)(smc + 24576);

    const int tid = threadIdx.x, lane = tid & 31, w = tid >> 5;
    const int bn = blockIdx.y, n = bn % NH, b = bn / NH;
    const int i0 = blockIdx.x * 64;

    const bf16* qwB = g_qw + (size_t)bn * SEQ * HD;
    const bf16* qrB = g_qr + (size_t)bn * SEQ * HD;
    const bf16* kB  = g_k  + (size_t)bn * SEQ * HD;
    const bf16* vB  = g_v  + (size_t)bn * SEQ * HD;
    const bf16* rhB = g_rh + (size_t)n * 2048 * HD;

    copy_tile64(sQw, qwB + (size_t)i0*HD, tid);
    copy_tile64(sQr, qrB + (size_t)i0*HD, tid);
    load_rh_tile(sRh, rhB, 961 - i0, tid);
    __syncthreads();

    unsigned qwA[4][4], qrA[4][4];
    {
        int arow = w*16 + (lane & 15);
        int csel = lane >> 4;
        #pragma unroll
        for (int ks = 0; ks < 4; ks++) {
            int ch = ks*2 + csel;
            unsigned off = ((ch ^ (arow & 7)) << 4) + arow*128;
            ldm_x4(qwA[ks][0], qwA[ks][1], qwA[ks][2], qwA[ks][3], s2u((char*)sQw + off));
            ldm_x4(qrA[ks][0], qrA[ks][1], qrA[ks][2], qrA[ks][3], s2u((char*)sQr + off));
        }
    }

    const int r0 = w*16 + (lane >> 2);
    const int q2 = 2*(lane & 3);

    float o[8][4] = {};
    float mrow0 = -INFINITY, mrow1 = -INFINITY, lrow0 = 0.f, lrow1 = 0.f;

    pos_mma_ring(sRh, ring, qrA, 961 - i0, lane, r0, q2);

    for (int j0 = 0; j0 < SEQ; j0 += 64) {
        __syncthreads();            // everyone done with frags/ring & prev tiles
        copy_tile64(sK, kB + (size_t)j0*HD, tid);
        copy_tile64(sV, vB + (size_t)j0*HD, tid);
        const int Tc = 1025 + j0 - i0;
        load_rh_tile(sRh, rhB, Tc, tid);
        __syncthreads();

        // content scores: qw @ k^T  (x4 B loads)
        float c[8][4] = {};
        #pragma unroll
        for (int nbp = 0; nbp < 4; nbp++) {
            int brow = nbp*16 + ((lane >> 4) << 3) + (lane & 7);
            #pragma unroll
            for (int ks = 0; ks < 4; ks++) {
                int ch = ks*2 + ((lane >> 3) & 1);
                unsigned b0, b1, b2, b3;
                ldm_x4(b0, b1, b2, b3,
                       s2u((char*)sK + brow*128 + ((ch ^ (brow & 7)) << 4)));
                mma_bf16(c[2*nbp],   qwA[ks], b0, b1);
                mma_bf16(c[2*nbp+1], qwA[ks], b2, b3);
            }
        }
        pos_mma_ring(sRh, ring, qrA, Tc, lane, r0, q2);
        __syncthreads();

        // gather positional band: t = 1024 + j - i
        #pragma unroll
        for (int nb = 0; nb < 8; nb++) {
            int jl = nb*8 + q2;
            int ta = 1024 + j0 + jl - (i0 + r0);
            c[nb][0] += ring[r0*RING_PITCH + (ta & 127)];
            c[nb][1] += ring[r0*RING_PITCH + ((ta + 1) & 127)];
            int tb = ta - 8;
            c[nb][2] += ring[(r0+8)*RING_PITCH + (tb & 127)];
            c[nb][3] += ring[(r0+8)*RING_PITCH + ((tb + 1) & 127)];
        }
        if (i0 == 0 && j0 == 960 && tid == 3) {
            float s = 0.f;
            #pragma unroll
            for (int d = 0; d < HD; d++)
                s += __bfloat162float(qrB[HD + d]) * __bfloat162float(rhB[d]);
            c[7][1] += s;
        }

        // online softmax
        float mx0 = -INFINITY, mx1 = -INFINITY;
        #pragma unroll
        for (int nb = 0; nb < 8; nb++) {
            mx0 = fmaxf(mx0, fmaxf(c[nb][0], c[nb][1]));
            mx1 = fmaxf(mx1, fmaxf(c[nb][2], c[nb][3]));
        }
        mx0 = fmaxf(mx0, __shfl_xor_sync(0xffffffffu, mx0, 1));
        mx0 = fmaxf(mx0, __shfl_xor_sync(0xffffffffu, mx0, 2));
        mx1 = fmaxf(mx1, __shfl_xor_sync(0xffffffffu, mx1, 1));
        mx1 = fmaxf(mx1, __shfl_xor_sync(0xffffffffu, mx1, 2));
        float mn0 = fmaxf(mrow0, mx0), mn1 = fmaxf(mrow1, mx1);
        float sc0 = __expf(mrow0 - mn0), sc1 = __expf(mrow1 - mn1);
        mrow0 = mn0; mrow1 = mn1;
        float s0 = 0.f, s1 = 0.f;
        #pragma unroll
        for (int nb = 0; nb < 8; nb++) {
            c[nb][0] = __expf(c[nb][0] - mn0); s0 += c[nb][0];
            c[nb][1] = __expf(c[nb][1] - mn0); s0 += c[nb][1];
            c[nb][2] = __expf(c[nb][2] - mn1); s1 += c[nb][2];
            c[nb][3] = __expf(c[nb][3] - mn1); s1 += c[nb][3];
        }
        s0 += __shfl_xor_sync(0xffffffffu, s0, 1);
        s0 += __shfl_xor_sync(0xffffffffu, s0, 2);
        s1 += __shfl_xor_sync(0xffffffffu, s1, 1);
        s1 += __shfl_xor_sync(0xffffffffu, s1, 2);
        lrow0 = lrow0*sc0 + s0; lrow1 = lrow1*sc1 + s1;
        #pragma unroll
        for (int nb = 0; nb < 8; nb++) {
            o[nb][0] *= sc0; o[nb][1] *= sc0;
            o[nb][2] *= sc1; o[nb][3] *= sc1;
        }

        // P -> A-frag repack
        unsigned pa[4][4];
        #pragma unroll
        for (int ks = 0; ks < 4; ks++) {
            pa[ks][0] = pk(c[2*ks][0],   c[2*ks][1]);
            pa[ks][1] = pk(c[2*ks][2],   c[2*ks][3]);
            pa[ks][2] = pk(c[2*ks+1][0], c[2*ks+1][1]);
            pa[ks][3] = pk(c[2*ks+1][2], c[2*ks+1][3]);
        }
        // o += P @ V  (x4 trans B loads)
        #pragma unroll
        for (int nbp = 0; nbp < 4; nbp++) {
            #pragma unroll
            for (int ks = 0; ks < 4; ks++) {
                int vrow = ks*16 + (lane & 15);
                int ch   = nbp*2 + (lane >> 4);
                unsigned b0, b1, b2, b3;
                ldm_x4t(b0, b1, b2, b3,
                        s2u((char*)sV + vrow*128 + ((ch ^ (vrow & 7)) << 4)));
                mma_bf16(o[2*nbp],   pa[ks], b0, b1);
                mma_bf16(o[2*nbp+1], pa[ks], b2, b3);
            }
        }
    }

    // epilogue: normalize + split into bf16 hi/lo
    float inv0 = 1.f / lrow0, inv1 = 1.f / lrow1;
    #pragma unroll
    for (int nb = 0; nb < 8; nb++) {
        int dd = nb*8 + q2;
        float a0 = o[nb][0]*inv0, a1 = o[nb][1]*inv0;
        float b0 = o[nb][2]*inv1, b1 = o[nb][3]*inv1;
        unsigned h0 = pk(a0, a1), h1 = pk(b0, b1);
        __nv_bfloat162 x0 = *(__nv_bfloat162*)&h0, x1 = *(__nv_bfloat162*)&h1;
        unsigned l0 = pk(a0 - __low2float(x0), a1 - __high2float(x0));
        unsigned l1 = pk(b0 - __low2float(x1), b1 - __high2float(x1));
        size_t ob0 = ((size_t)(b*SEQ + i0 + r0))*DM + n*HD + dd;
        size_t ob1 = ob0 + 8*DM;
        *(unsigned*)&g_avh[ob0] = h0;  *(unsigned*)&g_avl[ob0] = l0;
        *(unsigned*)&g_avh[ob1] = h1;  *(unsigned*)&g_avl[ob1] = l1;
    }
}

// ---------------------------------------------------------------------------
// K4: h = query + av @ Wo + bo  (split-bf16 MMA, x4 B loads).  grid (32, 12)
// ---------------------------------------------------------------------------
__global__ void __launch_bounds__(128) proj_kernel(
    const float* __restrict__ bo, const float* __restrict__ x)
{
    __shared__ bf16 sAh[64*64], sAl[64*64], sBh[64*64], sBl[64*64];
    const int tid = threadIdx.x, lane = tid & 31, w = tid >> 5;
    const int m0 = blockIdx.x * 64;
    const int o0 = blockIdx.y * 64;
    float c[8][4] = {};

    for (int kb = 0; kb < DM; kb += 64) {
        __syncthreads();
        copy_bf16_tile(sAh, g_avh + (size_t)m0*DM + kb, DM, tid);
        copy_bf16_tile(sAl, g_avl + (size_t)m0*DM + kb, DM, tid);
        copy_bf16_tile(sBh, g_woh + (size_t)kb*DM + o0, DM, tid);
        copy_bf16_tile(sBl, g_wol + (size_t)kb*DM + o0, DM, tid);
        __syncthreads();

        unsigned ah[4][4], al[4][4];
        int arow = w*16 + (lane & 15), csel = lane >> 4;
        #pragma unroll
        for (int ks = 0; ks < 4; ks++) {
            int ch = ks*2 + csel;
            unsigned off = arow*128 + ((ch ^ (arow&7)) << 4);
            ldm_x4(ah[ks][0], ah[ks][1], ah[ks][2], ah[ks][3], s2u((char*)sAh + off));
            ldm_x4(al[ks][0], al[ks][1], al[ks][2], al[ks][3], s2u((char*)sAl + off));
        }
        #pragma unroll
        for (int nbp = 0; nbp < 4; nbp++) {
            #pragma unroll
            for (int ks = 0; ks < 4; ks++) {
                int vrow = ks*16 + (lane & 15);
                int ch   = nbp*2 + (lane >> 4);
                unsigned off = vrow*128 + ((ch ^ (vrow&7)) << 4);
                unsigned bh0, bh1, bh2, bh3, bl0, bl1, bl2, bl3;
                ldm_x4t(bh0, bh1, bh2, bh3, s2u((char*)sBh + off));
                ldm_x4t(bl0, bl1, bl2, bl3, s2u((char*)sBl + off));
                mma_bf16(c[2*nbp],   ah[ks], bh0, bh1);
                mma_bf16(c[2*nbp],   al[ks], bh0, bh1);
                mma_bf16(c[2*nbp],   ah[ks], bl0, bl1);
                mma_bf16(c[2*nbp+1], ah[ks], bh2, bh3);
                mma_bf16(c[2*nbp+1], al[ks], bh2, bh3);
                mma_bf16(c[2*nbp+1], ah[ks], bl2, bl3);
            }
        }
    }

    const int r0 = w*16 + (lane >> 2), q2 = 2*(lane & 3);
    #pragma unroll
    for (int nb = 0; nb < 8; nb++) {
        int col = o0 + nb*8 + q2;
        float b0 = bo[col], b1 = bo[col+1];
        size_t ob0 = (size_t)(m0 + r0)*DM + col;
        size_t ob1 = ob0 + 8*DM;
        float2 q0 = *(const float2*)&x[ob0];
        float2 q1 = *(const float2*)&x[ob1];
        *(float2*)&g_h[ob0] = make_float2(c[nb][0] + b0 + q0.x, c[nb][1] + b1 + q0.y);
        *(float2*)&g_h[ob1] = make_float2(c[nb][2] + b0 + q1.x, c[nb][3] + b1 + q1.y);
    }
}

// ---------------------------------------------------------------------------
// K5: LayerNorm.  grid (2048), 256 threads
// ---------------------------------------------------------------------------
__global__ void __launch_bounds__(256) ln_kernel(
    const float* __restrict__ gamma, const float* __restrict__ beta,
    float* __restrict__ out)
{
    __shared__ float red[16];
    const int row = blockIdx.x;
    const int tid = threadIdx.x;
    const float* h = g_h + (size_t)row * DM;
    float v0 = h[tid], v1 = h[tid+256], v2 = h[tid+512];
    float s = v0+v1+v2, ss = v0*v0+v1*v1+v2*v2;
    #pragma unroll
    for (int o = 16; o >= 1; o >>= 1) {
        s  += __shfl_xor_sync(0xffffffffu, s,  o);
        ss += __shfl_xor_sync(0xffffffffu, ss, o);
    }
    if ((tid & 31) == 0) { red[tid>>5] = s; red[8 + (tid>>5)] = ss; }
    __syncthreads();
    if (tid < 32) {
        float a = (tid < 8)  ? red[tid]     : 0.f;
        float b = (tid < 8)  ? red[8+tid]   : 0.f;
        #pragma unroll
        for (int o = 4; o >= 1; o >>= 1) {
            a += __shfl_xor_sync(0xffffffffu, a, o);
            b += __shfl_xor_sync(0xffffffffu, b, o);
        }
        if (tid == 0) { red[0] = a; red[1] = b; }
    }
    __syncthreads();
    float mu  = red[0] * (1.f/DM);
    float var = red[1] * (1.f/DM) - mu*mu;
    float inv = rsqrtf(var + 1e-9f);
    out[(size_t)row*DM + tid]     = (v0 - mu)*inv*gamma[tid]     + beta[tid];
    out[(size_t)row*DM + tid+256] = (v1 - mu)*inv*gamma[tid+256] + beta[tid+256];
    out[(size_t)row*DM + tid+512] = (v2 - mu)*inv*gamma[tid+512] + beta[tid+512];
}

// ---------------------------------------------------------------------------
extern "C" void kernel_launch(void* const* d_in, const int* in_sizes, int n_in,
                              void* d_out, int out_size)
{
    const float* query = (const float*)d_in[0];
    const float* pe    = (const float*)d_in[1];
    const float* Wq    = (const float*)d_in[2];
    const float* Wk    = (const float*)d_in[3];
    const float* bk    = (const float*)d_in[4];
    const float* Wv    = (const float*)d_in[5];
    const float* bv    = (const float*)d_in[6];
    const float* rk    = (const float*)d_in[7];
    const float* rwb   = (const float*)d_in[8];
    const float* rrb   = (const float*)d_in[9];
    const float* Wo    = (const float*)d_in[10];
    const float* bo    = (const float*)d_in[11];
    const float* gamma = (const float*)d_in[12];
    const float* beta  = (const float*)d_in[13];
    float* out = (float*)d_out;

    static bool attr_set = false;
    if (!attr_set) {
        cudaFuncSetAttribute(attn_kernel,
            cudaFuncAttributeMaxDynamicSharedMemorySize, ATT_SMEM_BYTES);
        attr_set = true;
    }

    wo_prep<<<DM*DM/1024, 256>>>(Wo);
    qkv_kernel<<<dim3(32,12,3), 128>>>(query, Wq, Wk, bk, Wv, bv, rwb, rrb);
    rhead_kernel<<<dim3(32,12), 128>>>(pe, rk);
    attn_kernel<<<dim3(16,24), 128, ATT_SMEM_BYTES>>>();
    proj_kernel<<<dim3(32,12), 128>>>(bo, query);
    ln_kernel<<<2048, 256>>>(gamma, beta, out);
}

// round 8
// speedup vs baseline: 1.0755x; 1.0453x over previous
#include <cuda_runtime.h>
#include <cuda_bf16.h>
#include <math.h>

#define BD   2
#define SEQ  1024
#define DM   768
#define NH   12
#define HD   64
#define GD   192
#define ATT_SCALE 0.125f

typedef __nv_bfloat16 bf16;

// ------------------------------ scratch ------------------------------------
__device__ __align__(16) bf16 g_qw[BD*NH*SEQ*HD];
__device__ __align__(16) bf16 g_qr[BD*NH*SEQ*HD];
__device__ __align__(16) bf16 g_k [BD*NH*SEQ*HD];
__device__ __align__(16) bf16 g_v [BD*NH*SEQ*HD];
__device__ __align__(16) bf16 g_rh[NH*2048*HD];
__device__ __align__(16) bf16 g_avh[BD*SEQ*DM];
__device__ __align__(16) bf16 g_avl[BD*SEQ*DM];
__device__ __align__(16) bf16 g_woh[DM*DM];
__device__ __align__(16) bf16 g_wol[DM*DM];
__device__ float g_h [BD*SEQ*DM];

// ------------------------------ helpers ------------------------------------
__device__ __forceinline__ unsigned pk(float lo, float hi) {
    __nv_bfloat162 h = __floats2bfloat162_rn(lo, hi);
    return *(unsigned*)&h;
}
__device__ __forceinline__ unsigned s2u(const void* p) {
    return (unsigned)__cvta_generic_to_shared(p);
}
__device__ __forceinline__ void ldm_x4(unsigned& r0, unsigned& r1, unsigned& r2, unsigned& r3, unsigned a) {
    asm volatile("ldmatrix.sync.aligned.m8n8.x4.shared.b16 {%0,%1,%2,%3},[%4];"
                 : "=r"(r0), "=r"(r1), "=r"(r2), "=r"(r3) : "r"(a));
}
__device__ __forceinline__ void ldm_x4t(unsigned& r0, unsigned& r1, unsigned& r2, unsigned& r3, unsigned a) {
    asm volatile("ldmatrix.sync.aligned.m8n8.x4.trans.shared.b16 {%0,%1,%2,%3},[%4];"
                 : "=r"(r0), "=r"(r1), "=r"(r2), "=r"(r3) : "r"(a));
}
__device__ __forceinline__ void mma_bf16(float* c, const unsigned* a, unsigned b0, unsigned b1) {
    asm volatile("mma.sync.aligned.m16n8k16.row.col.f32.bf16.bf16.f32 "
                 "{%0,%1,%2,%3},{%4,%5,%6,%7},{%8,%9},{%0,%1,%2,%3};"
                 : "+f"(c[0]), "+f"(c[1]), "+f"(c[2]), "+f"(c[3])
                 : "r"(a[0]), "r"(a[1]), "r"(a[2]), "r"(a[3]), "r"(b0), "r"(b1));
}
__device__ __forceinline__ void cpa16(unsigned dst, const void* src, int sz) {
    asm volatile("cp.async.cg.shared.global [%0], [%1], 16, %2;"
                 :: "r"(dst), "l"(src), "r"(sz));
}
#define CP_COMMIT() asm volatile("cp.async.commit_group;")
template<int N> __device__ __forceinline__ void cp_wait() {
    asm volatile("cp.async.wait_group %0;" :: "n"(N));
}

// 64x64 fp32 tile -> bf16 swizzled smem
__device__ __forceinline__ void load_conv_tile(bf16* dst, const float* src, int ld,
                                               int valid_rows, int tid) {
    #pragma unroll
    for (int it = 0; it < 4; it++) {
        int c = tid + it*128, row = c >> 3, ch = c & 7;
        uint4 w = make_uint4(0u,0u,0u,0u);
        if (row < valid_rows) {
            const float* p = src + (size_t)row*ld + ch*8;
            float4 u = *(const float4*)p;
            float4 v = *(const float4*)(p+4);
            w.x = pk(u.x,u.y); w.y = pk(u.z,u.w);
            w.z = pk(v.x,v.y); w.w = pk(v.z,v.w);
        }
        *(uint4*)((char*)dst + row*128 + ((ch ^ (row&7)) << 4)) = w;
    }
}
__device__ __forceinline__ void copy_bf16_tile(bf16* dst, const bf16* src, int ld, int tid) {
    #pragma unroll
    for (int it = 0; it < 4; it++) {
        int c = tid + it*128, row = c >> 3, ch = c & 7;
        uint4 v = *(const uint4*)(src + (size_t)row*ld + ch*8);
        *(uint4*)((char*)dst + row*128 + ((ch ^ (row&7)) << 4)) = v;
    }
}

// one 64x64 tile: c += A(sA) @ B(sB)^T-layout, warp w rows w*16..+15. x4 B loads.
__device__ __forceinline__ void mma_tile(float (*c)[4], const bf16* sA, const bf16* sB,
                                         int lane, int w) {
    unsigned a[4][4];
    int arow = w*16 + (lane & 15), csel = lane >> 4;
    #pragma unroll
    for (int ks = 0; ks < 4; ks++) {
        int ch = ks*2 + csel;
        ldm_x4(a[ks][0], a[ks][1], a[ks][2], a[ks][3],
               s2u((const char*)sA + arow*128 + ((ch ^ (arow&7)) << 4)));
    }
    #pragma unroll
    for (int nbp = 0; nbp < 4; nbp++) {
        #pragma unroll
        for (int ks = 0; ks < 4; ks++) {
            int vrow = ks*16 + (lane & 15);
            int ch   = nbp*2 + (lane >> 4);
            unsigned b0, b1, b2, b3;
            ldm_x4t(b0, b1, b2, b3,
                    s2u((const char*)sB + vrow*128 + ((ch ^ (vrow&7)) << 4)));
            mma_bf16(c[2*nbp],   a[ks], b0, b1);
            mma_bf16(c[2*nbp+1], a[ks], b2, b3);
        }
    }
}

// ---------------------------------------------------------------------------
// K0: split Wo into bf16 hi/lo.  grid 576, 256 thr
// ---------------------------------------------------------------------------
__global__ void __launch_bounds__(256) wo_prep(const float* __restrict__ Wo)
{
    int i = (blockIdx.x*256 + threadIdx.x) * 4;
    float4 v = *(const float4*)&Wo[i];
    unsigned h0 = pk(v.x, v.y), h1 = pk(v.z, v.w);
    __nv_bfloat162 a = *(__nv_bfloat162*)&h0, b = *(__nv_bfloat162*)&h1;
    unsigned l0 = pk(v.x - __low2float(a), v.y - __high2float(a));
    unsigned l1 = pk(v.z - __low2float(b), v.w - __high2float(b));
    *(uint2*)&g_woh[i] = make_uint2(h0, h1);
    *(uint2*)&g_wol[i] = make_uint2(l0, l1);
}

// ---------------------------------------------------------------------------
// K1: grouped QKV projection + r_head GEMM fused launch. grid (32, 12, 4)
//     z in 0..2 -> q/k/v, z == 3 -> r_head
// ---------------------------------------------------------------------------
__global__ void __launch_bounds__(128) qkvr_kernel(
    const float* __restrict__ x,
    const float* __restrict__ Wq, const float* __restrict__ Wk, const float* __restrict__ bk,
    const float* __restrict__ Wv, const float* __restrict__ bv,
    const float* __restrict__ rwb, const float* __restrict__ rrb,
    const float* __restrict__ pe, const float* __restrict__ rk)
{
    __shared__ bf16 sA[64*64], sB[64*64];
    const int tid = threadIdx.x, lane = tid & 31, w = tid >> 5;
    const int z = blockIdx.z;
    float c[8][4] = {};
    const int r0 = w*16 + (lane >> 2), q2 = 2*(lane & 3);

    if (z == 3) {
        // r_head = pe @ rk
        const int t0 = blockIdx.x * 64;
        const int o0 = blockIdx.y * 64;
        const int vr = min(64, 2047 - t0);
        for (int kb = 0; kb < DM; kb += 64) {
            __syncthreads();
            load_conv_tile(sA, pe + (size_t)t0*DM + kb, DM, vr, tid);
            load_conv_tile(sB, rk + (size_t)kb*DM + o0, DM, 64, tid);
            __syncthreads();
            mma_tile(c, sA, sB, lane, w);
        }
        const int n = blockIdx.y;
        #pragma unroll
        for (int nb = 0; nb < 8; nb++) {
            int d = nb*8 + q2;
            size_t ob0 = ((size_t)n*2048 + t0 + r0)*HD + d;
            *(unsigned*)&g_rh[ob0]        = pk(c[nb][0], c[nb][1]);
            *(unsigned*)&g_rh[ob0 + 8*HD] = pk(c[nb][2], c[nb][3]);
        }
        return;
    }

    const int m0 = blockIdx.x * 64;
    const int g  = blockIdx.y / 3, oo0 = (blockIdx.y % 3) * 64;
    const float* W = ((z == 0) ? Wq : (z == 1) ? Wk : Wv) + g * GD * GD;

    for (int kb = 0; kb < GD; kb += 64) {
        __syncthreads();
        load_conv_tile(sA, x + (size_t)m0*DM + g*GD + kb, DM, 64, tid);
        load_conv_tile(sB, W + (size_t)kb*GD + oo0, GD, 64, tid);
        __syncthreads();
        mma_tile(c, sA, sB, lane, w);
    }

    const int n = blockIdx.y;
    const int o0g = g*GD + oo0;
    const int b = m0 >> 10;
    const int s0 = (m0 & 1023) + r0;
    #pragma unroll
    for (int nb = 0; nb < 8; nb++) {
        int d = nb*8 + q2, bi = o0g + d;
        size_t ob0 = (((size_t)(b*NH + n))*SEQ + s0)*HD + d;
        size_t ob1 = ob0 + 8*HD;
        if (z == 0) {
            float w0 = rwb[bi], w1 = rwb[bi+1], r0b = rrb[bi], r1b = rrb[bi+1];
            *(unsigned*)&g_qw[ob0] = pk((c[nb][0]+w0)*ATT_SCALE, (c[nb][1]+w1)*ATT_SCALE);
            *(unsigned*)&g_qw[ob1] = pk((c[nb][2]+w0)*ATT_SCALE, (c[nb][3]+w1)*ATT_SCALE);
            *(unsigned*)&g_qr[ob0] = pk((c[nb][0]+r0b)*ATT_SCALE, (c[nb][1]+r1b)*ATT_SCALE);
            *(unsigned*)&g_qr[ob1] = pk((c[nb][2]+r0b)*ATT_SCALE, (c[nb][3]+r1b)*ATT_SCALE);
        } else if (z == 1) {
            float b0 = bk[bi], b1 = bk[bi+1];
            *(unsigned*)&g_k[ob0] = pk(c[nb][0]+b0, c[nb][1]+b1);
            *(unsigned*)&g_k[ob1] = pk(c[nb][2]+b0, c[nb][3]+b1);
        } else {
            float b0 = bv[bi], b1 = bv[bi+1];
            *(unsigned*)&g_v[ob0] = pk(c[nb][0]+b0, c[nb][1]+b1);
            *(unsigned*)&g_v[ob1] = pk(c[nb][2]+b0, c[nb][3]+b1);
        }
    }
}

// ---------------------------------------------------------------------------
// K3: flash attention with cp.async 2-stage pipeline.
// smem: K0 K1 Rh0 Rh1 V (8KB each) + fp32 ring
// ---------------------------------------------------------------------------
#define RING_PITCH 132
#define ATT_SMEM_BYTES (40960 + 64*RING_PITCH*4)   // 74752

__device__ __forceinline__ void copy_tile64(bf16* dst, const bf16* src, int tid) {
    #pragma unroll
    for (int k = 0; k < 4; k++) {
        int c = tid + k*128, row = c >> 3, ch = c & 7;
        uint4 v = *(const uint4*)(src + (size_t)row*64 + ch*8);
        *(uint4*)((char*)dst + row*128 + ((ch ^ (row & 7)) << 4)) = v;
    }
}
__device__ __forceinline__ void load_rh_tile(bf16* dst, const bf16* src, int Tc, int tid) {
    #pragma unroll
    for (int k = 0; k < 4; k++) {
        int c = tid + k*128, row = c >> 3, ch = c & 7;
        int t = Tc + row;
        uint4 v = make_uint4(0u,0u,0u,0u);
        if (t < 2048) v = *(const uint4*)(src + (size_t)t*64 + ch*8);
        *(uint4*)((char*)dst + row*128 + ((ch ^ (row & 7)) << 4)) = v;
    }
}
__device__ __forceinline__ void async_tile64(bf16* dst, const bf16* src, int tid) {
    #pragma unroll
    for (int k = 0; k < 4; k++) {
        int c = tid + k*128, row = c >> 3, ch = c & 7;
        cpa16(s2u((char*)dst + row*128 + ((ch ^ (row & 7)) << 4)),
              src + (size_t)row*64 + ch*8, 16);
    }
}
__device__ __forceinline__ void async_rh(bf16* dst, const bf16* src, int Tc, int tid) {
    #pragma unroll
    for (int k = 0; k < 4; k++) {
        int c = tid + k*128, row = c >> 3, ch = c & 7;
        int t = Tc + row;
        int sz = (t < 2048) ? 16 : 0;
        const bf16* p = src + (size_t)(t < 2048 ? t : 2047)*64 + ch*8;
        cpa16(s2u((char*)dst + row*128 + ((ch ^ (row & 7)) << 4)), p, sz);
    }
}

// pos' columns for window Tc..Tc+63 into the ring (x4 B loads)
__device__ __forceinline__ void pos_mma_ring(
    const bf16* sRh, float* ring, const unsigned (*qrA)[4],
    int Tc, int lane, int r0, int q2)
{
    #pragma unroll
    for (int nbp = 0; nbp < 4; nbp++) {
        float p0[4] = {0.f,0.f,0.f,0.f}, p1[4] = {0.f,0.f,0.f,0.f};
        int brow = nbp*16 + ((lane >> 4) << 3) + (lane & 7);
        #pragma unroll
        for (int ks = 0; ks < 4; ks++) {
            int ch = ks*2 + ((lane >> 3) & 1);
            unsigned b0, b1, b2, b3;
            ldm_x4(b0, b1, b2, b3,
                   s2u((const char*)sRh + brow*128 + ((ch ^ (brow & 7)) << 4)));
            mma_bf16(p0, qrA[ks], b0, b1);
            mma_bf16(p1, qrA[ks], b2, b3);
        }
        #pragma unroll
        for (int h = 0; h < 2; h++) {
            const float* pc = h ? p1 : p0;
            int s0 = (Tc + (nbp*2+h)*8 + q2) & 127;
            int s1 = (s0 + 1) & 127;
            ring[r0*RING_PITCH + s0]     = pc[0];
            ring[r0*RING_PITCH + s1]     = pc[1];
            ring[(r0+8)*RING_PITCH + s0] = pc[2];
            ring[(r0+8)*RING_PITCH + s1] = pc[3];
        }
    }
}

__global__ void __launch_bounds__(128, 3) attn_kernel()
{
    extern __shared__ char smc[];
    bf16*  sK0  = (bf16*)(smc);
    bf16*  sK1  = (bf16*)(smc + 8192);
    bf16*  sRh0 = (bf16*)(smc + 16384);
    bf16*  sRh1 = (bf16*)(smc + 24576);
    bf16*  sV   = (bf16*)(smc + 32768);
    float* ring = (float*)(smc + 40960);

    const int tid = threadIdx.x, lane = tid & 31, w = tid >> 5;
    const int bn = blockIdx.y, n = bn % NH, b = bn / NH;
    const int i0 = blockIdx.x * 64;

    const bf16* qwB = g_qw + (size_t)bn * SEQ * HD;
    const bf16* qrB = g_qr + (size_t)bn * SEQ * HD;
    const bf16* kB  = g_k  + (size_t)bn * SEQ * HD;
    const bf16* vB  = g_v  + (size_t)bn * SEQ * HD;
    const bf16* rhB = g_rh + (size_t)n * 2048 * HD;

    // prologue: Qw -> sK1 area, Qr -> sV area, pre-window rh -> sRh0
    copy_tile64(sK1, qwB + (size_t)i0*HD, tid);
    copy_tile64(sV,  qrB + (size_t)i0*HD, tid);
    load_rh_tile(sRh0, rhB, 961 - i0, tid);
    __syncthreads();

    // prefetch iter0: K -> sK0, rh(1025-i0) -> sRh1    (group A_-1)
    async_tile64(sK0, kB, tid);
    async_rh(sRh1, rhB, 1025 - i0, tid);
    CP_COMMIT();

    unsigned qwA[4][4], qrA[4][4];
    {
        int arow = w*16 + (lane & 15);
        int csel = lane >> 4;
        #pragma unroll
        for (int ks = 0; ks < 4; ks++) {
            int ch = ks*2 + csel;
            unsigned off = ((ch ^ (arow & 7)) << 4) + arow*128;
            ldm_x4(qwA[ks][0], qwA[ks][1], qwA[ks][2], qwA[ks][3], s2u((char*)sK1 + off));
            ldm_x4(qrA[ks][0], qrA[ks][1], qrA[ks][2], qrA[ks][3], s2u((char*)sV  + off));
        }
    }

    const int r0 = w*16 + (lane >> 2);
    const int q2 = 2*(lane & 3);

    float o[8][4] = {};
    float mrow0 = -INFINITY, mrow1 = -INFINITY, lrow0 = 0.f, lrow1 = 0.f;

    // first half of the pos' window (from sRh0)
    pos_mma_ring(sRh0, ring, qrA, 961 - i0, lane, r0, q2);

    for (int it = 0; it < 16; it++) {
        const int j0 = it * 64;
        bf16* Kc = (it & 1) ? sK1 : sK0;
        bf16* Kn = (it & 1) ? sK0 : sK1;
        bf16* Rc = (it & 1) ? sRh0 : sRh1;
        bf16* Rn = (it & 1) ? sRh1 : sRh0;

        __syncthreads();   // everyone done with prev stage + prologue reads
        if (it < 15) {
            async_tile64(Kn, kB + (size_t)(j0+64)*HD, tid);
            async_rh(Rn, rhB, 1025 + (j0+64) - i0, tid);
            CP_COMMIT();
        }
        async_tile64(sV, vB + (size_t)j0*HD, tid);   // V for THIS iter
        CP_COMMIT();
        if (it < 15) cp_wait<2>(); else cp_wait<1>();
        __syncthreads();   // K/Rh of this iter visible

        // content scores: qw @ k^T
        float c[8][4] = {};
        #pragma unroll
        for (int nbp = 0; nbp < 4; nbp++) {
            int brow = nbp*16 + ((lane >> 4) << 3) + (lane & 7);
            #pragma unroll
            for (int ks = 0; ks < 4; ks++) {
                int ch = ks*2 + ((lane >> 3) & 1);
                unsigned b0, b1, b2, b3;
                ldm_x4(b0, b1, b2, b3,
                       s2u((char*)Kc + brow*128 + ((ch ^ (brow & 7)) << 4)));
                mma_bf16(c[2*nbp],   qwA[ks], b0, b1);
                mma_bf16(c[2*nbp+1], qwA[ks], b2, b3);
            }
        }
        pos_mma_ring(Rc, ring, qrA, 1025 + j0 - i0, lane, r0, q2);
        if (it < 15) cp_wait<1>(); else cp_wait<0>();
        __syncthreads();   // ring + V visible

        // gather positional band: t = 1024 + j - i
        #pragma unroll
        for (int nb = 0; nb < 8; nb++) {
            int jl = nb*8 + q2;
            int ta = 1024 + j0 + jl - (i0 + r0);
            c[nb][0] += ring[r0*RING_PITCH + (ta & 127)];
            c[nb][1] += ring[r0*RING_PITCH + ((ta + 1) & 127)];
            int tb = ta - 8;
            c[nb][2] += ring[(r0+8)*RING_PITCH + (tb & 127)];
            c[nb][3] += ring[(r0+8)*RING_PITCH + ((tb + 1) & 127)];
        }
        if (i0 == 0 && j0 == 960 && tid == 3) {
            float s = 0.f;
            #pragma unroll
            for (int d = 0; d < HD; d++)
                s += __bfloat162float(qrB[HD + d]) * __bfloat162float(rhB[d]);
            c[7][1] += s;
        }

        // online softmax
        float mx0 = -INFINITY, mx1 = -INFINITY;
        #pragma unroll
        for (int nb = 0; nb < 8; nb++) {
            mx0 = fmaxf(mx0, fmaxf(c[nb][0], c[nb][1]));
            mx1 = fmaxf(mx1, fmaxf(c[nb][2], c[nb][3]));
        }
        mx0 = fmaxf(mx0, __shfl_xor_sync(0xffffffffu, mx0, 1));
        mx0 = fmaxf(mx0, __shfl_xor_sync(0xffffffffu, mx0, 2));
        mx1 = fmaxf(mx1, __shfl_xor_sync(0xffffffffu, mx1, 1));
        mx1 = fmaxf(mx1, __shfl_xor_sync(0xffffffffu, mx1, 2));
        float mn0 = fmaxf(mrow0, mx0), mn1 = fmaxf(mrow1, mx1);
        float sc0 = __expf(mrow0 - mn0), sc1 = __expf(mrow1 - mn1);
        mrow0 = mn0; mrow1 = mn1;
        float s0 = 0.f, s1 = 0.f;
        #pragma unroll
        for (int nb = 0; nb < 8; nb++) {
            c[nb][0] = __expf(c[nb][0] - mn0); s0 += c[nb][0];
            c[nb][1] = __expf(c[nb][1] - mn0); s0 += c[nb][1];
            c[nb][2] = __expf(c[nb][2] - mn1); s1 += c[nb][2];
            c[nb][3] = __expf(c[nb][3] - mn1); s1 += c[nb][3];
        }
        s0 += __shfl_xor_sync(0xffffffffu, s0, 1);
        s0 += __shfl_xor_sync(0xffffffffu, s0, 2);
        s1 += __shfl_xor_sync(0xffffffffu, s1, 1);
        s1 += __shfl_xor_sync(0xffffffffu, s1, 2);
        lrow0 = lrow0*sc0 + s0; lrow1 = lrow1*sc1 + s1;
        #pragma unroll
        for (int nb = 0; nb < 8; nb++) {
            o[nb][0] *= sc0; o[nb][1] *= sc0;
            o[nb][2] *= sc1; o[nb][3] *= sc1;
        }

        // P -> A-frag repack
        unsigned pa[4][4];
        #pragma unroll
        for (int ks = 0; ks < 4; ks++) {
            pa[ks][0] = pk(c[2*ks][0],   c[2*ks][1]);
            pa[ks][1] = pk(c[2*ks][2],   c[2*ks][3]);
            pa[ks][2] = pk(c[2*ks+1][0], c[2*ks+1][1]);
            pa[ks][3] = pk(c[2*ks+1][2], c[2*ks+1][3]);
        }
        // o += P @ V
        #pragma unroll
        for (int nbp = 0; nbp < 4; nbp++) {
            #pragma unroll
            for (int ks = 0; ks < 4; ks++) {
                int vrow = ks*16 + (lane & 15);
                int ch   = nbp*2 + (lane >> 4);
                unsigned b0, b1, b2, b3;
                ldm_x4t(b0, b1, b2, b3,
                        s2u((char*)sV + vrow*128 + ((ch ^ (vrow & 7)) << 4)));
                mma_bf16(o[2*nbp],   pa[ks], b0, b1);
                mma_bf16(o[2*nbp+1], pa[ks], b2, b3);
            }
        }
    }

    // epilogue: normalize + split into bf16 hi/lo
    float inv0 = 1.f / lrow0, inv1 = 1.f / lrow1;
    #pragma unroll
    for (int nb = 0; nb < 8; nb++) {
        int dd = nb*8 + q2;
        float a0 = o[nb][0]*inv0, a1 = o[nb][1]*inv0;
        float b0 = o[nb][2]*inv1, b1 = o[nb][3]*inv1;
        unsigned h0 = pk(a0, a1), h1 = pk(b0, b1);
        __nv_bfloat162 x0 = *(__nv_bfloat162*)&h0, x1 = *(__nv_bfloat162*)&h1;
        unsigned l0 = pk(a0 - __low2float(x0), a1 - __high2float(x0));
        unsigned l1 = pk(b0 - __low2float(x1), b1 - __high2float(x1));
        size_t ob0 = ((size_t)(b*SEQ + i0 + r0))*DM + n*HD + dd;
        size_t ob1 = ob0 + 8*DM;
        *(unsigned*)&g_avh[ob0] = h0;  *(unsigned*)&g_avl[ob0] = l0;
        *(unsigned*)&g_avh[ob1] = h1;  *(unsigned*)&g_avl[ob1] = l1;
    }
}

// ---------------------------------------------------------------------------
// K4: h = query + av @ Wo + bo  (split-bf16 MMA).  grid (32, 12)
// ---------------------------------------------------------------------------
__global__ void __launch_bounds__(128) proj_kernel(
    const float* __restrict__ bo, const float* __restrict__ x)
{
    __shared__ bf16 sAh[64*64], sAl[64*64], sBh[64*64], sBl[64*64];
    const int tid = threadIdx.x, lane = tid & 31, w = tid >> 5;
    const int m0 = blockIdx.x * 64;
    const int o0 = blockIdx.y * 64;
    float c[8][4] = {};

    for (int kb = 0; kb < DM; kb += 64) {
        __syncthreads();
        copy_bf16_tile(sAh, g_avh + (size_t)m0*DM + kb, DM, tid);
        copy_bf16_tile(sAl, g_avl + (size_t)m0*DM + kb, DM, tid);
        copy_bf16_tile(sBh, g_woh + (size_t)kb*DM + o0, DM, tid);
        copy_bf16_tile(sBl, g_wol + (size_t)kb*DM + o0, DM, tid);
        __syncthreads();

        unsigned ah[4][4], al[4][4];
        int arow = w*16 + (lane & 15), csel = lane >> 4;
        #pragma unroll
        for (int ks = 0; ks < 4; ks++) {
            int ch = ks*2 + csel;
            unsigned off = arow*128 + ((ch ^ (arow&7)) << 4);
            ldm_x4(ah[ks][0], ah[ks][1], ah[ks][2], ah[ks][3], s2u((char*)sAh + off));
            ldm_x4(al[ks][0], al[ks][1], al[ks][2], al[ks][3], s2u((char*)sAl + off));
        }
        #pragma unroll
        for (int nbp = 0; nbp < 4; nbp++) {
            #pragma unroll
            for (int ks = 0; ks < 4; ks++) {
                int vrow = ks*16 + (lane & 15);
                int ch   = nbp*2 + (lane >> 4);
                unsigned off = vrow*128 + ((ch ^ (vrow&7)) << 4);
                unsigned bh0, bh1, bh2, bh3, bl0, bl1, bl2, bl3;
                ldm_x4t(bh0, bh1, bh2, bh3, s2u((char*)sBh + off));
                ldm_x4t(bl0, bl1, bl2, bl3, s2u((char*)sBl + off));
                mma_bf16(c[2*nbp],   ah[ks], bh0, bh1);
                mma_bf16(c[2*nbp],   al[ks], bh0, bh1);
                mma_bf16(c[2*nbp],   ah[ks], bl0, bl1);
                mma_bf16(c[2*nbp+1], ah[ks], bh2, bh3);
                mma_bf16(c[2*nbp+1], al[ks], bh2, bh3);
                mma_bf16(c[2*nbp+1], ah[ks], bl2, bl3);
            }
        }
    }

    const int r0 = w*16 + (lane >> 2), q2 = 2*(lane & 3);
    #pragma unroll
    for (int nb = 0; nb < 8; nb++) {
        int col = o0 + nb*8 + q2;
        float b0 = bo[col], b1 = bo[col+1];
        size_t ob0 = (size_t)(m0 + r0)*DM + col;
        size_t ob1 = ob0 + 8*DM;
        float2 q0 = *(const float2*)&x[ob0];
        float2 q1 = *(const float2*)&x[ob1];
        *(float2*)&g_h[ob0] = make_float2(c[nb][0] + b0 + q0.x, c[nb][1] + b1 + q0.y);
        *(float2*)&g_h[ob1] = make_float2(c[nb][2] + b0 + q1.x, c[nb][3] + b1 + q1.y);
    }
}

// ---------------------------------------------------------------------------
// K5: LayerNorm.  grid (2048), 256 threads
// ---------------------------------------------------------------------------
__global__ void __launch_bounds__(256) ln_kernel(
    const float* __restrict__ gamma, const float* __restrict__ beta,
    float* __restrict__ out)
{
    __shared__ float red[16];
    const int row = blockIdx.x;
    const int tid = threadIdx.x;
    const float* h = g_h + (size_t)row * DM;
    float v0 = h[tid], v1 = h[tid+256], v2 = h[tid+512];
    float s = v0+v1+v2, ss = v0*v0+v1*v1+v2*v2;
    #pragma unroll
    for (int o = 16; o >= 1; o >>= 1) {
        s  += __shfl_xor_sync(0xffffffffu, s,  o);
        ss += __shfl_xor_sync(0xffffffffu, ss, o);
    }
    if ((tid & 31) == 0) { red[tid>>5] = s; red[8 + (tid>>5)] = ss; }
    __syncthreads();
    if (tid < 32) {
        float a = (tid < 8)  ? red[tid]     : 0.f;
        float b = (tid < 8)  ? red[8+tid]   : 0.f;
        #pragma unroll
        for (int o = 4; o >= 1; o >>= 1) {
            a += __shfl_xor_sync(0xffffffffu, a, o);
            b += __shfl_xor_sync(0xffffffffu, b, o);
        }
        if (tid == 0) { red[0] = a; red[1] = b; }
    }
    __syncthreads();
    float mu  = red[0] * (1.f/DM);
    float var = red[1] * (1.f/DM) - mu*mu;
    float inv = rsqrtf(var + 1e-9f);
    out[(size_t)row*DM + tid]     = (v0 - mu)*inv*gamma[tid]     + beta[tid];
    out[(size_t)row*DM + tid+256] = (v1 - mu)*inv*gamma[tid+256] + beta[tid+256];
    out[(size_t)row*DM + tid+512] = (v2 - mu)*inv*gamma[tid+512] + beta[tid+512];
}

// ---------------------------------------------------------------------------
extern "C" void kernel_launch(void* const* d_in, const int* in_sizes, int n_in,
                              void* d_out, int out_size)
{
    const float* query = (const float*)d_in[0];
    const float* pe    = (const float*)d_in[1];
    const float* Wq    = (const float*)d_in[2];
    const float* Wk    = (const float*)d_in[3];
    const float* bk    = (const float*)d_in[4];
    const float* Wv    = (const float*)d_in[5];
    const float* bv    = (const float*)d_in[6];
    const float* rk    = (const float*)d_in[7];
    const float* rwb   = (const float*)d_in[8];
    const float* rrb   = (const float*)d_in[9];
    const float* Wo    = (const float*)d_in[10];
    const float* bo    = (const float*)d_in[11];
    const float* gamma = (const float*)d_in[12];
    const float* beta  = (const float*)d_in[13];
    float* out = (float*)d_out;

    static bool attr_set = false;
    if (!attr_set) {
        cudaFuncSetAttribute(attn_kernel,
            cudaFuncAttributeMaxDynamicSharedMemorySize, ATT_SMEM_BYTES);
        attr_set = true;
    }

    wo_prep<<<DM*DM/1024, 256>>>(Wo);
    qkvr_kernel<<<dim3(32,12,4), 128>>>(query, Wq, Wk, bk, Wv, bv, rwb, rrb, pe, rk);
    attn_kernel<<<dim3(16,24), 128, ATT_SMEM_BYTES>>>();
    proj_kernel<<<dim3(32,12), 128>>>(bo, query);
    ln_kernel<<<2048, 256>>>(gamma, beta, out);
}

// round 9
// speedup vs baseline: 1.3682x; 1.2722x over previous
#include <cuda_runtime.h>
#include <cuda_bf16.h>
#include <math.h>

#define BD   2
#define SEQ  1024
#define DM   768
#define NH   12
#define HD   64
#define GD   192
#define ATT_SCALE 0.125f

typedef __nv_bfloat16 bf16;

// ------------------------------ scratch ------------------------------------
__device__ __align__(16) bf16 g_qw[BD*NH*SEQ*HD];
__device__ __align__(16) bf16 g_qr[BD*NH*SEQ*HD];
__device__ __align__(16) bf16 g_k [BD*NH*SEQ*HD];
__device__ __align__(16) bf16 g_v [BD*NH*SEQ*HD];
__device__ __align__(16) bf16 g_rh[NH*2048*HD];
__device__ __align__(16) bf16 g_avh[BD*SEQ*DM];
__device__ __align__(16) bf16 g_avl[BD*SEQ*DM];
__device__ __align__(16) bf16 g_woh[DM*DM];
__device__ __align__(16) bf16 g_wol[DM*DM];
__device__ __align__(16) bf16 g_xb [BD*SEQ*DM];
__device__ __align__(16) bf16 g_peb[2047*DM + 64];
__device__ __align__(16) bf16 g_rkb[DM*DM];
__device__ __align__(16) bf16 g_wb [3*4*GD*GD];
__device__ float g_h [BD*SEQ*DM];

// ------------------------------ helpers ------------------------------------
__device__ __forceinline__ unsigned pk(float lo, float hi) {
    __nv_bfloat162 h = __floats2bfloat162_rn(lo, hi);
    return *(unsigned*)&h;
}
__device__ __forceinline__ unsigned s2u(const void* p) {
    return (unsigned)__cvta_generic_to_shared(p);
}
__device__ __forceinline__ void ldm_x4(unsigned& r0, unsigned& r1, unsigned& r2, unsigned& r3, unsigned a) {
    asm volatile("ldmatrix.sync.aligned.m8n8.x4.shared.b16 {%0,%1,%2,%3},[%4];"
                 : "=r"(r0), "=r"(r1), "=r"(r2), "=r"(r3) : "r"(a));
}
__device__ __forceinline__ void ldm_x4t(unsigned& r0, unsigned& r1, unsigned& r2, unsigned& r3, unsigned a) {
    asm volatile("ldmatrix.sync.aligned.m8n8.x4.trans.shared.b16 {%0,%1,%2,%3},[%4];"
                 : "=r"(r0), "=r"(r1), "=r"(r2), "=r"(r3) : "r"(a));
}
__device__ __forceinline__ void mma_bf16(float* c, const unsigned* a, unsigned b0, unsigned b1) {
    asm volatile("mma.sync.aligned.m16n8k16.row.col.f32.bf16.bf16.f32 "
                 "{%0,%1,%2,%3},{%4,%5,%6,%7},{%8,%9},{%0,%1,%2,%3};"
                 : "+f"(c[0]), "+f"(c[1]), "+f"(c[2]), "+f"(c[3])
                 : "r"(a[0]), "r"(a[1]), "r"(a[2]), "r"(a[3]), "r"(b0), "r"(b1));
}
__device__ __forceinline__ void cpa16(unsigned dst, const void* src, int sz) {
    asm volatile("cp.async.cg.shared.global [%0], [%1], 16, %2;"
                 :: "r"(dst), "l"(src), "r"(sz));
}
#define CP_COMMIT() asm volatile("cp.async.commit_group;")
template<int N> __device__ __forceinline__ void cp_wait() {
    asm volatile("cp.async.wait_group %0;" :: "n"(N));
}

// async 64x64 bf16 tile load into swizzled smem; rows >= maxrow zero-filled
__device__ __forceinline__ void async_bf16_tile(bf16* dst, const bf16* src, int ld,
                                                int maxrow, int tid) {
    #pragma unroll
    for (int it = 0; it < 4; it++) {
        int c = tid + it*128, row = c >> 3, ch = c & 7;
        int sz = (row < maxrow) ? 16 : 0;
        int ar = (row < maxrow) ? row : (maxrow - 1);
        cpa16(s2u((char*)dst + row*128 + ((ch ^ (row&7)) << 4)),
              src + (size_t)ar*ld + ch*8, sz);
    }
}

// one 64x64 tile: c += A(sA) @ B(sB), warp w rows w*16..+15. x4 B loads.
__device__ __forceinline__ void mma_tile(float (*c)[4], const bf16* sA, const bf16* sB,
                                         int lane, int w) {
    unsigned a[4][4];
    int arow = w*16 + (lane & 15), csel = lane >> 4;
    #pragma unroll
    for (int ks = 0; ks < 4; ks++) {
        int ch = ks*2 + csel;
        ldm_x4(a[ks][0], a[ks][1], a[ks][2], a[ks][3],
               s2u((const char*)sA + arow*128 + ((ch ^ (arow&7)) << 4)));
    }
    #pragma unroll
    for (int nbp = 0; nbp < 4; nbp++) {
        #pragma unroll
        for (int ks = 0; ks < 4; ks++) {
            int vrow = ks*16 + (lane & 15);
            int ch   = nbp*2 + (lane >> 4);
            unsigned b0, b1, b2, b3;
            ldm_x4t(b0, b1, b2, b3,
                    s2u((const char*)sB + vrow*128 + ((ch ^ (vrow&7)) << 4)));
            mma_bf16(c[2*nbp],   a[ks], b0, b1);
            mma_bf16(c[2*nbp+1], a[ks], b2, b3);
        }
    }
}

// ---------------------------------------------------------------------------
// K0a: fp32 -> bf16 conversions (x, pe, rk, Wq, Wk, Wv).  grid (256, 6)
// ---------------------------------------------------------------------------
__global__ void __launch_bounds__(256) conv_prep(
    const float* __restrict__ x,  const float* __restrict__ pe,
    const float* __restrict__ rk, const float* __restrict__ Wq,
    const float* __restrict__ Wk, const float* __restrict__ Wv)
{
    const int seg = blockIdx.y;
    const float* src; bf16* dst; int n4;
    switch (seg) {
        case 0: src = x;  dst = g_xb;  n4 = BD*SEQ*DM/4;   break;
        case 1: src = pe; dst = g_peb; n4 = 2047*DM/4;     break;
        case 2: src = rk; dst = g_rkb; n4 = DM*DM/4;       break;
        case 3: src = Wq; dst = g_wb;            n4 = GD*GD; break;
        case 4: src = Wk; dst = g_wb + 4*GD*GD;  n4 = GD*GD; break;
        default: src = Wv; dst = g_wb + 8*GD*GD; n4 = GD*GD; break;
    }
    for (int i = blockIdx.x*256 + threadIdx.x; i < n4; i += gridDim.x*256) {
        float4 v = *(const float4*)&src[i*4];
        *(uint2*)&dst[i*4] = make_uint2(pk(v.x, v.y), pk(v.z, v.w));
    }
}

// ---------------------------------------------------------------------------
// K0b: split Wo into bf16 hi/lo.  grid 576, 256 thr
// ---------------------------------------------------------------------------
__global__ void __launch_bounds__(256) wo_prep(const float* __restrict__ Wo)
{
    int i = (blockIdx.x*256 + threadIdx.x) * 4;
    float4 v = *(const float4*)&Wo[i];
    unsigned h0 = pk(v.x, v.y), h1 = pk(v.z, v.w);
    __nv_bfloat162 a = *(__nv_bfloat162*)&h0, b = *(__nv_bfloat162*)&h1;
    unsigned l0 = pk(v.x - __low2float(a), v.y - __high2float(a));
    unsigned l1 = pk(v.z - __low2float(b), v.w - __high2float(b));
    *(uint2*)&g_woh[i] = make_uint2(h0, h1);
    *(uint2*)&g_wol[i] = make_uint2(l0, l1);
}

// ---------------------------------------------------------------------------
// K1: grouped QKV + r_head GEMMs, cp.async pipelined. grid (32, 12, 4)
// ---------------------------------------------------------------------------
__global__ void __launch_bounds__(128) qkvr_kernel(
    const float* __restrict__ bk, const float* __restrict__ bv,
    const float* __restrict__ rwb, const float* __restrict__ rrb)
{
    __shared__ bf16 sA[2][64*64], sB[2][64*64];
    const int tid = threadIdx.x, lane = tid & 31, w = tid >> 5;
    const int z = blockIdx.z;
    float c[8][4] = {};
    const int r0 = w*16 + (lane >> 2), q2 = 2*(lane & 3);

    const bf16 *srcA, *srcB;
    int ldA, ldB, maxA, nk;
    if (z == 3) {
        const int t0 = blockIdx.x * 64, o0 = blockIdx.y * 64;
        srcA = g_peb + (size_t)t0*DM;  ldA = DM;  maxA = min(64, 2047 - t0);
        srcB = g_rkb + o0;             ldB = DM;
        nk = DM/64;
    } else {
        const int m0 = blockIdx.x * 64;
        const int g  = blockIdx.y / 3, oo0 = (blockIdx.y % 3) * 64;
        srcA = g_xb + (size_t)m0*DM + g*GD;                 ldA = DM; maxA = 64;
        srcB = g_wb + (size_t)z*4*GD*GD + g*GD*GD + oo0;    ldB = GD;
        nk = GD/64;
    }

    async_bf16_tile(sA[0], srcA, ldA, maxA, tid);
    async_bf16_tile(sB[0], srcB, ldB, 64, tid);
    CP_COMMIT();

    for (int i = 0; i < nk; i++) {
        int cur = i & 1, nxt = cur ^ 1;
        if (i + 1 < nk) {
            async_bf16_tile(sA[nxt], srcA + (i+1)*64, ldA, maxA, tid);
            async_bf16_tile(sB[nxt], srcB + (size_t)(i+1)*64*ldB, ldB, 64, tid);
            CP_COMMIT();
            cp_wait<1>();
        } else cp_wait<0>();
        __syncthreads();
        mma_tile(c, sA[cur], sB[cur], lane, w);
        __syncthreads();
    }

    if (z == 3) {
        const int t0 = blockIdx.x * 64, n = blockIdx.y;
        #pragma unroll
        for (int nb = 0; nb < 8; nb++) {
            int d = nb*8 + q2;
            size_t ob0 = ((size_t)n*2048 + t0 + r0)*HD + d;
            *(unsigned*)&g_rh[ob0]        = pk(c[nb][0], c[nb][1]);
            *(unsigned*)&g_rh[ob0 + 8*HD] = pk(c[nb][2], c[nb][3]);
        }
        return;
    }

    const int m0 = blockIdx.x * 64;
    const int g  = blockIdx.y / 3, oo0 = (blockIdx.y % 3) * 64;
    const int n = blockIdx.y;
    const int o0g = g*GD + oo0;
    const int b = m0 >> 10;
    const int s0 = (m0 & 1023) + r0;
    #pragma unroll
    for (int nb = 0; nb < 8; nb++) {
        int d = nb*8 + q2, bi = o0g + d;
        size_t ob0 = (((size_t)(b*NH + n))*SEQ + s0)*HD + d;
        size_t ob1 = ob0 + 8*HD;
        if (z == 0) {
            float w0 = rwb[bi], w1 = rwb[bi+1], r0b = rrb[bi], r1b = rrb[bi+1];
            *(unsigned*)&g_qw[ob0] = pk((c[nb][0]+w0)*ATT_SCALE, (c[nb][1]+w1)*ATT_SCALE);
            *(unsigned*)&g_qw[ob1] = pk((c[nb][2]+w0)*ATT_SCALE, (c[nb][3]+w1)*ATT_SCALE);
            *(unsigned*)&g_qr[ob0] = pk((c[nb][0]+r0b)*ATT_SCALE, (c[nb][1]+r1b)*ATT_SCALE);
            *(unsigned*)&g_qr[ob1] = pk((c[nb][2]+r0b)*ATT_SCALE, (c[nb][3]+r1b)*ATT_SCALE);
        } else if (z == 1) {
            float b0 = bk[bi], b1 = bk[bi+1];
            *(unsigned*)&g_k[ob0] = pk(c[nb][0]+b0, c[nb][1]+b1);
            *(unsigned*)&g_k[ob1] = pk(c[nb][2]+b0, c[nb][3]+b1);
        } else {
            float b0 = bv[bi], b1 = bv[bi+1];
            *(unsigned*)&g_v[ob0] = pk(c[nb][0]+b0, c[nb][1]+b1);
            *(unsigned*)&g_v[ob1] = pk(c[nb][2]+b0, c[nb][3]+b1);
        }
    }
}

// ---------------------------------------------------------------------------
// K3: flash attention with cp.async 2-stage pipeline (unchanged from R8).
// ---------------------------------------------------------------------------
#define RING_PITCH 132
#define ATT_SMEM_BYTES (40960 + 64*RING_PITCH*4)   // 74752

__device__ __forceinline__ void copy_tile64(bf16* dst, const bf16* src, int tid) {
    #pragma unroll
    for (int k = 0; k < 4; k++) {
        int c = tid + k*128, row = c >> 3, ch = c & 7;
        uint4 v = *(const uint4*)(src + (size_t)row*64 + ch*8);
        *(uint4*)((char*)dst + row*128 + ((ch ^ (row & 7)) << 4)) = v;
    }
}
__device__ __forceinline__ void load_rh_tile(bf16* dst, const bf16* src, int Tc, int tid) {
    #pragma unroll
    for (int k = 0; k < 4; k++) {
        int c = tid + k*128, row = c >> 3, ch = c & 7;
        int t = Tc + row;
        uint4 v = make_uint4(0u,0u,0u,0u);
        if (t < 2048) v = *(const uint4*)(src + (size_t)t*64 + ch*8);
        *(uint4*)((char*)dst + row*128 + ((ch ^ (row & 7)) << 4)) = v;
    }
}
__device__ __forceinline__ void async_tile64(bf16* dst, const bf16* src, int tid) {
    #pragma unroll
    for (int k = 0; k < 4; k++) {
        int c = tid + k*128, row = c >> 3, ch = c & 7;
        cpa16(s2u((char*)dst + row*128 + ((ch ^ (row & 7)) << 4)),
              src + (size_t)row*64 + ch*8, 16);
    }
}
__device__ __forceinline__ void async_rh(bf16* dst, const bf16* src, int Tc, int tid) {
    #pragma unroll
    for (int k = 0; k < 4; k++) {
        int c = tid + k*128, row = c >> 3, ch = c & 7;
        int t = Tc + row;
        int sz = (t < 2048) ? 16 : 0;
        const bf16* p = src + (size_t)(t < 2048 ? t : 2047)*64 + ch*8;
        cpa16(s2u((char*)dst + row*128 + ((ch ^ (row & 7)) << 4)), p, sz);
    }
}

__device__ __forceinline__ void pos_mma_ring(
    const bf16* sRh, float* ring, const unsigned (*qrA)[4],
    int Tc, int lane, int r0, int q2)
{
    #pragma unroll
    for (int nbp = 0; nbp < 4; nbp++) {
        float p0[4] = {0.f,0.f,0.f,0.f}, p1[4] = {0.f,0.f,0.f,0.f};
        int brow = nbp*16 + ((lane >> 4) << 3) + (lane & 7);
        #pragma unroll
        for (int ks = 0; ks < 4; ks++) {
            int ch = ks*2 + ((lane >> 3) & 1);
            unsigned b0, b1, b2, b3;
            ldm_x4(b0, b1, b2, b3,
                   s2u((const char*)sRh + brow*128 + ((ch ^ (brow & 7)) << 4)));
            mma_bf16(p0, qrA[ks], b0, b1);
            mma_bf16(p1, qrA[ks], b2, b3);
        }
        #pragma unroll
        for (int h = 0; h < 2; h++) {
            const float* pc = h ? p1 : p0;
            int s0 = (Tc + (nbp*2+h)*8 + q2) & 127;
            int s1 = (s0 + 1) & 127;
            ring[r0*RING_PITCH + s0]     = pc[0];
            ring[r0*RING_PITCH + s1]     = pc[1];
            ring[(r0+8)*RING_PITCH + s0] = pc[2];
            ring[(r0+8)*RING_PITCH + s1] = pc[3];
        }
    }
}

__global__ void __launch_bounds__(128, 3) attn_kernel()
{
    extern __shared__ char smc[];
    bf16*  sK0  = (bf16*)(smc);
    bf16*  sK1  = (bf16*)(smc + 8192);
    bf16*  sRh0 = (bf16*)(smc + 16384);
    bf16*  sRh1 = (bf16*)(smc + 24576);
    bf16*  sV   = (bf16*)(smc + 32768);
    float* ring = (float*)(smc + 40960);

    const int tid = threadIdx.x, lane = tid & 31, w = tid >> 5;
    const int bn = blockIdx.y, n = bn % NH, b = bn / NH;
    const int i0 = blockIdx.x * 64;

    const bf16* qwB = g_qw + (size_t)bn * SEQ * HD;
    const bf16* qrB = g_qr + (size_t)bn * SEQ * HD;
    const bf16* kB  = g_k  + (size_t)bn * SEQ * HD;
    const bf16* vB  = g_v  + (size_t)bn * SEQ * HD;
    const bf16* rhB = g_rh + (size_t)n * 2048 * HD;

    copy_tile64(sK1, qwB + (size_t)i0*HD, tid);
    copy_tile64(sV,  qrB + (size_t)i0*HD, tid);
    load_rh_tile(sRh0, rhB, 961 - i0, tid);
    __syncthreads();

    async_tile64(sK0, kB, tid);
    async_rh(sRh1, rhB, 1025 - i0, tid);
    CP_COMMIT();

    unsigned qwA[4][4], qrA[4][4];
    {
        int arow = w*16 + (lane & 15);
        int csel = lane >> 4;
        #pragma unroll
        for (int ks = 0; ks < 4; ks++) {
            int ch = ks*2 + csel;
            unsigned off = ((ch ^ (arow & 7)) << 4) + arow*128;
            ldm_x4(qwA[ks][0], qwA[ks][1], qwA[ks][2], qwA[ks][3], s2u((char*)sK1 + off));
            ldm_x4(qrA[ks][0], qrA[ks][1], qrA[ks][2], qrA[ks][3], s2u((char*)sV  + off));
        }
    }

    const int r0 = w*16 + (lane >> 2);
    const int q2 = 2*(lane & 3);

    float o[8][4] = {};
    float mrow0 = -INFINITY, mrow1 = -INFINITY, lrow0 = 0.f, lrow1 = 0.f;

    pos_mma_ring(sRh0, ring, qrA, 961 - i0, lane, r0, q2);

    for (int it = 0; it < 16; it++) {
        const int j0 = it * 64;
        bf16* Kc = (it & 1) ? sK1 : sK0;
        bf16* Kn = (it & 1) ? sK0 : sK1;
        bf16* Rc = (it & 1) ? sRh0 : sRh1;
        bf16* Rn = (it & 1) ? sRh1 : sRh0;

        __syncthreads();
        if (it < 15) {
            async_tile64(Kn, kB + (size_t)(j0+64)*HD, tid);
            async_rh(Rn, rhB, 1025 + (j0+64) - i0, tid);
            CP_COMMIT();
        }
        async_tile64(sV, vB + (size_t)j0*HD, tid);
        CP_COMMIT();
        if (it < 15) cp_wait<2>(); else cp_wait<1>();
        __syncthreads();

        float c[8][4] = {};
        #pragma unroll
        for (int nbp = 0; nbp < 4; nbp++) {
            int brow = nbp*16 + ((lane >> 4) << 3) + (lane & 7);
            #pragma unroll
            for (int ks = 0; ks < 4; ks++) {
                int ch = ks*2 + ((lane >> 3) & 1);
                unsigned b0, b1, b2, b3;
                ldm_x4(b0, b1, b2, b3,
                       s2u((char*)Kc + brow*128 + ((ch ^ (brow & 7)) << 4)));
                mma_bf16(c[2*nbp],   qwA[ks], b0, b1);
                mma_bf16(c[2*nbp+1], qwA[ks], b2, b3);
            }
        }
        pos_mma_ring(Rc, ring, qrA, 1025 + j0 - i0, lane, r0, q2);
        if (it < 15) cp_wait<1>(); else cp_wait<0>();
        __syncthreads();

        #pragma unroll
        for (int nb = 0; nb < 8; nb++) {
            int jl = nb*8 + q2;
            int ta = 1024 + j0 + jl - (i0 + r0);
            c[nb][0] += ring[r0*RING_PITCH + (ta & 127)];
            c[nb][1] += ring[r0*RING_PITCH + ((ta + 1) & 127)];
            int tb = ta - 8;
            c[nb][2] += ring[(r0+8)*RING_PITCH + (tb & 127)];
            c[nb][3] += ring[(r0+8)*RING_PITCH + ((tb + 1) & 127)];
        }
        if (i0 == 0 && j0 == 960 && tid == 3) {
            float s = 0.f;
            #pragma unroll
            for (int d = 0; d < HD; d++)
                s += __bfloat162float(qrB[HD + d]) * __bfloat162float(rhB[d]);
            c[7][1] += s;
        }

        float mx0 = -INFINITY, mx1 = -INFINITY;
        #pragma unroll
        for (int nb = 0; nb < 8; nb++) {
            mx0 = fmaxf(mx0, fmaxf(c[nb][0], c[nb][1]));
            mx1 = fmaxf(mx1, fmaxf(c[nb][2], c[nb][3]));
        }
        mx0 = fmaxf(mx0, __shfl_xor_sync(0xffffffffu, mx0, 1));
        mx0 = fmaxf(mx0, __shfl_xor_sync(0xffffffffu, mx0, 2));
        mx1 = fmaxf(mx1, __shfl_xor_sync(0xffffffffu, mx1, 1));
        mx1 = fmaxf(mx1, __shfl_xor_sync(0xffffffffu, mx1, 2));
        float mn0 = fmaxf(mrow0, mx0), mn1 = fmaxf(mrow1, mx1);
        float sc0 = __expf(mrow0 - mn0), sc1 = __expf(mrow1 - mn1);
        mrow0 = mn0; mrow1 = mn1;
        float s0 = 0.f, s1 = 0.f;
        #pragma unroll
        for (int nb = 0; nb < 8; nb++) {
            c[nb][0] = __expf(c[nb][0] - mn0); s0 += c[nb][0];
            c[nb][1] = __expf(c[nb][1] - mn0); s0 += c[nb][1];
            c[nb][2] = __expf(c[nb][2] - mn1); s1 += c[nb][2];
            c[nb][3] = __expf(c[nb][3] - mn1); s1 += c[nb][3];
        }
        s0 += __shfl_xor_sync(0xffffffffu, s0, 1);
        s0 += __shfl_xor_sync(0xffffffffu, s0, 2);
        s1 += __shfl_xor_sync(0xffffffffu, s1, 1);
        s1 += __shfl_xor_sync(0xffffffffu, s1, 2);
        lrow0 = lrow0*sc0 + s0; lrow1 = lrow1*sc1 + s1;
        #pragma unroll
        for (int nb = 0; nb < 8; nb++) {
            o[nb][0] *= sc0; o[nb][1] *= sc0;
            o[nb][2] *= sc1; o[nb][3] *= sc1;
        }

        unsigned pa[4][4];
        #pragma unroll
        for (int ks = 0; ks < 4; ks++) {
            pa[ks][0] = pk(c[2*ks][0],   c[2*ks][1]);
            pa[ks][1] = pk(c[2*ks][2],   c[2*ks][3]);
            pa[ks][2] = pk(c[2*ks+1][0], c[2*ks+1][1]);
            pa[ks][3] = pk(c[2*ks+1][2], c[2*ks+1][3]);
        }
        #pragma unroll
        for (int nbp = 0; nbp < 4; nbp++) {
            #pragma unroll
            for (int ks = 0; ks < 4; ks++) {
                int vrow = ks*16 + (lane & 15);
                int ch   = nbp*2 + (lane >> 4);
                unsigned b0, b1, b2, b3;
                ldm_x4t(b0, b1, b2, b3,
                        s2u((char*)sV + vrow*128 + ((ch ^ (vrow & 7)) << 4)));
                mma_bf16(o[2*nbp],   pa[ks], b0, b1);
                mma_bf16(o[2*nbp+1], pa[ks], b2, b3);
            }
        }
    }

    float inv0 = 1.f / lrow0, inv1 = 1.f / lrow1;
    #pragma unroll
    for (int nb = 0; nb < 8; nb++) {
        int dd = nb*8 + q2;
        float a0 = o[nb][0]*inv0, a1 = o[nb][1]*inv0;
        float b0 = o[nb][2]*inv1, b1 = o[nb][3]*inv1;
        unsigned h0 = pk(a0, a1), h1 = pk(b0, b1);
        __nv_bfloat162 x0 = *(__nv_bfloat162*)&h0, x1 = *(__nv_bfloat162*)&h1;
        unsigned l0 = pk(a0 - __low2float(x0), a1 - __high2float(x0));
        unsigned l1 = pk(b0 - __low2float(x1), b1 - __high2float(x1));
        size_t ob0 = ((size_t)(b*SEQ + i0 + r0))*DM + n*HD + dd;
        size_t ob1 = ob0 + 8*DM;
        *(unsigned*)&g_avh[ob0] = h0;  *(unsigned*)&g_avl[ob0] = l0;
        *(unsigned*)&g_avh[ob1] = h1;  *(unsigned*)&g_avl[ob1] = l1;
    }
}

// ---------------------------------------------------------------------------
// K4: h = query + av @ Wo + bo  (split-bf16 MMA, cp.async pipelined).
// smem: 2 stages x 4 tiles x 8KB = 64KB dynamic.  grid (32, 12)
// ---------------------------------------------------------------------------
#define PROJ_SMEM_BYTES 65536

__global__ void __launch_bounds__(128, 3) proj_kernel(
    const float* __restrict__ bo, const float* __restrict__ x)
{
    extern __shared__ char psm[];
    const int tid = threadIdx.x, lane = tid & 31, w = tid >> 5;
    const int m0 = blockIdx.x * 64;
    const int o0 = blockIdx.y * 64;
    float c[8][4] = {};

    const bf16* srcAh = g_avh + (size_t)m0*DM;
    const bf16* srcAl = g_avl + (size_t)m0*DM;
    const bf16* srcBh = g_woh + o0;
    const bf16* srcBl = g_wol + o0;

    // stage s base: psm + s*32768; tiles Ah,Al,Bh,Bl at +0,+8192,+16384,+24576
    #define PT(s, t) ((bf16*)(psm + (s)*32768 + (t)*8192))

    async_bf16_tile(PT(0,0), srcAh, DM, 64, tid);
    async_bf16_tile(PT(0,1), srcAl, DM, 64, tid);
    async_bf16_tile(PT(0,2), srcBh, DM, 64, tid);
    async_bf16_tile(PT(0,3), srcBl, DM, 64, tid);
    CP_COMMIT();

    const int NK = DM/64;
    for (int i = 0; i < NK; i++) {
        int cur = i & 1, nxt = cur ^ 1;
        if (i + 1 < NK) {
            int kb = (i+1)*64;
            async_bf16_tile(PT(nxt,0), srcAh + kb, DM, 64, tid);
            async_bf16_tile(PT(nxt,1), srcAl + kb, DM, 64, tid);
            async_bf16_tile(PT(nxt,2), srcBh + (size_t)kb*DM, DM, 64, tid);
            async_bf16_tile(PT(nxt,3), srcBl + (size_t)kb*DM, DM, 64, tid);
            CP_COMMIT();
            cp_wait<1>();
        } else cp_wait<0>();
        __syncthreads();

        bf16* sAh = PT(cur,0); bf16* sAl = PT(cur,1);
        bf16* sBh = PT(cur,2); bf16* sBl = PT(cur,3);

        unsigned ah[4][4], al[4][4];
        int arow = w*16 + (lane & 15), csel = lane >> 4;
        #pragma unroll
        for (int ks = 0; ks < 4; ks++) {
            int ch = ks*2 + csel;
            unsigned off = arow*128 + ((ch ^ (arow&7)) << 4);
            ldm_x4(ah[ks][0], ah[ks][1], ah[ks][2], ah[ks][3], s2u((char*)sAh + off));
            ldm_x4(al[ks][0], al[ks][1], al[ks][2], al[ks][3], s2u((char*)sAl + off));
        }
        #pragma unroll
        for (int nbp = 0; nbp < 4; nbp++) {
            #pragma unroll
            for (int ks = 0; ks < 4; ks++) {
                int vrow = ks*16 + (lane & 15);
                int ch   = nbp*2 + (lane >> 4);
                unsigned off = vrow*128 + ((ch ^ (vrow&7)) << 4);
                unsigned bh0, bh1, bh2, bh3, bl0, bl1, bl2, bl3;
                ldm_x4t(bh0, bh1, bh2, bh3, s2u((char*)sBh + off));
                ldm_x4t(bl0, bl1, bl2, bl3, s2u((char*)sBl + off));
                mma_bf16(c[2*nbp],   ah[ks], bh0, bh1);
                mma_bf16(c[2*nbp],   al[ks], bh0, bh1);
                mma_bf16(c[2*nbp],   ah[ks], bl0, bl1);
                mma_bf16(c[2*nbp+1], ah[ks], bh2, bh3);
                mma_bf16(c[2*nbp+1], al[ks], bh2, bh3);
                mma_bf16(c[2*nbp+1], ah[ks], bl2, bl3);
            }
        }
        __syncthreads();
    }
    #undef PT

    const int r0 = w*16 + (lane >> 2), q2 = 2*(lane & 3);
    #pragma unroll
    for (int nb = 0; nb < 8; nb++) {
        int col = o0 + nb*8 + q2;
        float b0 = bo[col], b1 = bo[col+1];
        size_t ob0 = (size_t)(m0 + r0)*DM + col;
        size_t ob1 = ob0 + 8*DM;
        float2 q0 = *(const float2*)&x[ob0];
        float2 q1 = *(const float2*)&x[ob1];
        *(float2*)&g_h[ob0] = make_float2(c[nb][0] + b0 + q0.x, c[nb][1] + b1 + q0.y);
        *(float2*)&g_h[ob1] = make_float2(c[nb][2] + b0 + q1.x, c[nb][3] + b1 + q1.y);
    }
}

// ---------------------------------------------------------------------------
// K5: LayerNorm.  grid (2048), 256 threads
// ---------------------------------------------------------------------------
__global__ void __launch_bounds__(256) ln_kernel(
    const float* __restrict__ gamma, const float* __restrict__ beta,
    float* __restrict__ out)
{
    __shared__ float red[16];
    const int row = blockIdx.x;
    const int tid = threadIdx.x;
    const float* h = g_h + (size_t)row * DM;
    float v0 = h[tid], v1 = h[tid+256], v2 = h[tid+512];
    float s = v0+v1+v2, ss = v0*v0+v1*v1+v2*v2;
    #pragma unroll
    for (int o = 16; o >= 1; o >>= 1) {
        s  += __shfl_xor_sync(0xffffffffu, s,  o);
        ss += __shfl_xor_sync(0xffffffffu, ss, o);
    }
    if ((tid & 31) == 0) { red[tid>>5] = s; red[8 + (tid>>5)] = ss; }
    __syncthreads();
    if (tid < 32) {
        float a = (tid < 8)  ? red[tid]     : 0.f;
        float b = (tid < 8)  ? red[8+tid]   : 0.f;
        #pragma unroll
        for (int o = 4; o >= 1; o >>= 1) {
            a += __shfl_xor_sync(0xffffffffu, a, o);
            b += __shfl_xor_sync(0xffffffffu, b, o);
        }
        if (tid == 0) { red[0] = a; red[1] = b; }
    }
    __syncthreads();
    float mu  = red[0] * (1.f/DM);
    float var = red[1] * (1.f/DM) - mu*mu;
    float inv = rsqrtf(var + 1e-9f);
    out[(size_t)row*DM + tid]     = (v0 - mu)*inv*gamma[tid]     + beta[tid];
    out[(size_t)row*DM + tid+256] = (v1 - mu)*inv*gamma[tid+256] + beta[tid+256];
    out[(size_t)row*DM + tid+512] = (v2 - mu)*inv*gamma[tid+512] + beta[tid+512];
}

// ---------------------------------------------------------------------------
extern "C" void kernel_launch(void* const* d_in, const int* in_sizes, int n_in,
                              void* d_out, int out_size)
{
    const float* query = (const float*)d_in[0];
    const float* pe    = (const float*)d_in[1];
    const float* Wq    = (const float*)d_in[2];
    const float* Wk    = (const float*)d_in[3];
    const float* bk    = (const float*)d_in[4];
    const float* Wv    = (const float*)d_in[5];
    const float* bv    = (const float*)d_in[6];
    const float* rk    = (const float*)d_in[7];
    const float* rwb   = (const float*)d_in[8];
    const float* rrb   = (const float*)d_in[9];
    const float* Wo    = (const float*)d_in[10];
    const float* bo    = (const float*)d_in[11];
    const float* gamma = (const float*)d_in[12];
    const float* beta  = (const float*)d_in[13];
    float* out = (float*)d_out;

    static bool attr_set = false;
    if (!attr_set) {
        cudaFuncSetAttribute(attn_kernel,
            cudaFuncAttributeMaxDynamicSharedMemorySize, ATT_SMEM_BYTES);
        cudaFuncSetAttribute(proj_kernel,
            cudaFuncAttributeMaxDynamicSharedMemorySize, PROJ_SMEM_BYTES);
        attr_set = true;
    }

    conv_prep<<<dim3(256,6), 256>>>(query, pe, rk, Wq, Wk, Wv);
    wo_prep<<<DM*DM/1024, 256>>>(Wo);
    qkvr_kernel<<<dim3(32,12,4), 128>>>(bk, bv, rwb, rrb);
    attn_kernel<<<dim3(16,24), 128, ATT_SMEM_BYTES>>>();
    proj_kernel<<<dim3(32,12), 128, PROJ_SMEM_BYTES>>>(bo, query);
    ln_kernel<<<2048, 256>>>(gamma, beta, out);
}